// round 3
// baseline (speedup 1.0000x reference)
#include <cuda_runtime.h>
#include <cuda_bf16.h>
#include <math.h>

// Problem constants
#define BATCH 8
#define NSTMT 80
#define NNODE 81
#define HID   256
#define H4    1024
#define NSTEP 8
#define VOCAB 30000
#define CHAINS (NNODE*BATCH)   // 648
#define NB 296                  // persistent grid (2 blocks/SM guaranteed co-resident)

// ---------------- device scratch (allocation-free) ----------------
static __device__ float d_SKIP[BATCH*NNODE*NNODE*HID];   // [b][start][pos][h]
static __device__ float d_KEYS[BATCH*NNODE*NNODE*HID];
static __device__ float d_STMT[BATCH*NSTMT*HID];
static __device__ float d_TMPH[BATCH*NSTMT*HID];
static __device__ float d_XG0 [BATCH*NSTMT*H4];          // stmt@skWx0 + skb0 (interleaved)
// ping-pong raw skip-LSTM state
static __device__ float d_RC0[2*CHAINS*HID];
static __device__ float d_RH0[2*CHAINS*HID];
static __device__ float d_RC1[2*CHAINS*HID];
static __device__ float d_RH1[2*CHAINS*HID];
static __device__ float d_MU [CHAINS];
static __device__ float d_RSD[CHAINS];
static __device__ float d_HC [CHAINS*H4];   // exec state: c0,h0,c1,h1
static __device__ float d_Q  [CHAINS*HID];
static __device__ float d_T  [BATCH*NNODE*NNODE];
static __device__ float d_P  [CHAINS];
static __device__ float d_XHE[CHAINS*512];  // [x_in, h0prop]
static __device__ float d_XH2[CHAINS*512];  // [h0new, h1prop]
static __device__ float d_CPR[CHAINS*512];  // [c0prop, c1prop]
// interleaved weights (col' = 4h + gate)
static __device__ float d_WST0[HID*H4];
static __device__ float d_WST1[HID*H4];
static __device__ float d_WSKX0[HID*H4];
static __device__ float d_WSKH0[HID*H4];
static __device__ float d_WSK1[512*H4];   // [skWx1; skWh1]
static __device__ float d_WEX0[512*H4];   // [exWx0; exWh0]
static __device__ float d_WEX1[512*H4];   // [exWx1; exWh1]
static __device__ float d_BST0[H4], d_BST1[H4], d_BSK0[H4], d_BSK1[H4], d_BEX0[H4], d_BEX1[H4];
// grid barrier state
static __device__ unsigned g_cnt;
static __device__ unsigned g_gen;

// ---------------- helpers ----------------
__device__ __forceinline__ float sigf(float x){ return 1.f/(1.f+__expf(-x)); }
__device__ __forceinline__ float ftanh(float x){ return 1.f - 2.f/(__expf(2.f*x)+1.f); }

__device__ __forceinline__ void grid_barrier() {
    __syncthreads();
    if (threadIdx.x == 0) {
        unsigned gen = *(volatile unsigned*)&g_gen;
        __threadfence();
        if (atomicAdd(&g_cnt, 1u) == (unsigned)(gridDim.x - 1)) {
            atomicExch(&g_cnt, 0u);
            __threadfence();
            atomicExch(&g_gen, gen + 1u);
        } else {
            while (*(volatile unsigned*)&g_gen == gen) { __nanosleep(64); }
        }
        __threadfence();
    }
    __syncthreads();
}

// ---------------- init / weight prep ----------------
__global__ void init_kernel() {
    int stride = gridDim.x * blockDim.x;
    int gid = blockIdx.x * blockDim.x + threadIdx.x;
    for (int i = gid; i < BATCH*NNODE*NNODE*HID; i += stride) d_SKIP[i] = 0.f;
    for (int i = gid; i < CHAINS*H4; i += stride) d_HC[i] = 0.f;
    for (int i = gid; i < CHAINS; i += stride) d_P[i] = (i % NNODE == 0) ? 1.f : 0.f;
    if (gid == 0) { g_cnt = 0u; g_gen = 0u; }
}

__global__ void build_w(const float* __restrict__ stWx, const float* __restrict__ skWx,
                        const float* __restrict__ skWh, const float* __restrict__ exWx,
                        const float* __restrict__ exWh) {
    int i = blockIdx.x*256 + threadIdx.x;
    if (i >= 512*H4) return;
    int k = i >> 10, n = i & 1023;
    int h = n >> 2, g = n & 3;
    int sc = h + 256*g;                 // source (non-interleaved) column
    const int L1 = 256*H4;
    d_WSK1[i] = (k < 256) ? skWx[L1 + k*H4 + sc] : skWh[L1 + (k-256)*H4 + sc];
    d_WEX0[i] = (k < 256) ? exWx[k*H4 + sc]      : exWh[(k-256)*H4 + sc];
    d_WEX1[i] = (k < 256) ? exWx[L1 + k*H4 + sc] : exWh[L1 + (k-256)*H4 + sc];
    if (k < 256) {
        d_WST0[k*H4 + n]  = stWx[k*H4 + sc];
        d_WST1[k*H4 + n]  = stWx[L1 + k*H4 + sc];
        d_WSKX0[k*H4 + n] = skWx[k*H4 + sc];
        d_WSKH0[k*H4 + n] = skWh[k*H4 + sc];
    }
}

__global__ void build_b(const float* __restrict__ st_b, const float* __restrict__ sk_b,
                        const float* __restrict__ ex_b) {
    int i = blockIdx.x*256 + threadIdx.x;
    if (i >= H4) return;
    int h = i >> 2, g = i & 3;
    int sc = h + 256*g;
    d_BST0[i] = st_b[sc];       d_BST1[i] = st_b[H4 + sc];
    d_BSK0[i] = sk_b[sc];       d_BSK1[i] = sk_b[H4 + sc];
    d_BEX0[i] = ex_b[sc];       d_BEX1[i] = ex_b[H4 + sc];
}

// ---------------- fused GEMM + LSTM-cell epilogue (non-persistent path) ----------------
// C[M,N] = A[M,K] @ B[K,N]; 32x64 tile, 128 threads, 4x4/thread, double-buffered.
// EPI: 0 plain(+bias), 1 stmt-cell(zero carry), 4 exec L0, 5 exec L1
template<int EPI>
__global__ void __launch_bounds__(128) gemm_epi(
    const float* __restrict__ A, const float* __restrict__ B,
    const float* __restrict__ bias, float* __restrict__ C,
    int M, int K, int N,
    float* __restrict__ p1, float* __restrict__ p2, float* __restrict__ p3)
{
    __shared__ float As[2][16][36];
    __shared__ float Bs[2][16][64];
    const int tid = threadIdx.x;
    const int tx = tid & 15, ty = tid >> 4;
    const int row0 = blockIdx.y * 32;
    const int col0 = blockIdx.x * 64;
    const int T = K >> 4;
    const int am = tid >> 2;
    const int ak = (tid & 3) << 2;
    const int bk = tid >> 4;
    const int bn = (tid & 15) << 2;
    const int gmA = row0 + am;
    float acc[4][4] = {};
    float4 ra, rb0, rb1;
    ra = (gmA < M) ? *(const float4*)&A[gmA*K + ak] : make_float4(0.f,0.f,0.f,0.f);
    rb0 = *(const float4*)&B[bk*N + col0 + bn];
    rb1 = *(const float4*)&B[(bk+8)*N + col0 + bn];
    As[0][ak][am]=ra.x; As[0][ak+1][am]=ra.y; As[0][ak+2][am]=ra.z; As[0][ak+3][am]=ra.w;
    *(float4*)&Bs[0][bk][bn] = rb0;
    *(float4*)&Bs[0][bk+8][bn] = rb1;
    __syncthreads();
    for (int t = 0; t < T; t++) {
        const int p = t & 1;
        if (t+1 < T) {
            int k0 = (t+1) << 4;
            ra = (gmA < M) ? *(const float4*)&A[gmA*K + k0 + ak] : make_float4(0.f,0.f,0.f,0.f);
            rb0 = *(const float4*)&B[(k0+bk)*N + col0 + bn];
            rb1 = *(const float4*)&B[(k0+bk+8)*N + col0 + bn];
        }
        #pragma unroll
        for (int kk = 0; kk < 16; kk++) {
            float4 b4 = *(const float4*)&Bs[p][kk][tx<<2];
            float4 a4 = *(const float4*)&As[p][kk][ty<<2];
            acc[0][0]+=a4.x*b4.x; acc[0][1]+=a4.x*b4.y; acc[0][2]+=a4.x*b4.z; acc[0][3]+=a4.x*b4.w;
            acc[1][0]+=a4.y*b4.x; acc[1][1]+=a4.y*b4.y; acc[1][2]+=a4.y*b4.z; acc[1][3]+=a4.y*b4.w;
            acc[2][0]+=a4.z*b4.x; acc[2][1]+=a4.z*b4.y; acc[2][2]+=a4.z*b4.z; acc[2][3]+=a4.z*b4.w;
            acc[3][0]+=a4.w*b4.x; acc[3][1]+=a4.w*b4.y; acc[3][2]+=a4.w*b4.z; acc[3][3]+=a4.w*b4.w;
        }
        if (t+1 < T) {
            const int q = p ^ 1;
            As[q][ak][am]=ra.x; As[q][ak+1][am]=ra.y; As[q][ak+2][am]=ra.z; As[q][ak+3][am]=ra.w;
            *(float4*)&Bs[q][bk][bn] = rb0;
            *(float4*)&Bs[q][bk+8][bn] = rb1;
            __syncthreads();
        }
    }

    if (EPI == 0) {
        float4 bv = make_float4(0.f,0.f,0.f,0.f);
        if (bias) bv = *(const float4*)&bias[col0 + (tx<<2)];
        #pragma unroll
        for (int i = 0; i < 4; i++) {
            int gm = row0 + (ty<<2) + i;
            if (gm >= M) continue;
            float4 v = make_float4(acc[i][0]+bv.x, acc[i][1]+bv.y, acc[i][2]+bv.z, acc[i][3]+bv.w);
            *(float4*)&C[gm*N + col0 + (tx<<2)] = v;
        }
    } else {
        const int h = (col0 >> 2) + tx;          // hidden unit index
        float4 bv = make_float4(0.f,0.f,0.f,0.f);
        if (bias) bv = *(const float4*)&bias[h<<2];
        #pragma unroll
        for (int i = 0; i < 4; i++) {
            int gm = row0 + (ty<<2) + i;
            if (gm >= M) continue;
            float gi = acc[i][0]+bv.x, gf = acc[i][1]+bv.y, gg = acc[i][2]+bv.z, go = acc[i][3]+bv.w;
            if (EPI == 1) {
                float cv = sigf(gi)*ftanh(gg);
                p1[gm*HID + h] = sigf(go)*ftanh(cv);
            } else if (EPI == 4) {
                float cp = p1[gm*512 + h];    // c0 prop
                float cv = sigf(gf)*cp + sigf(gi)*ftanh(gg);
                float hv = sigf(go)*ftanh(cv);
                p2[gm*H4 + h]       = cv;     // HC c0
                p2[gm*H4 + HID + h] = hv;     // HC h0
                p3[gm*512 + h]      = hv;     // XH2 first half
            } else {
                float cp = p1[gm*512 + HID + h];  // c1 prop
                float cv = sigf(gf)*cp + sigf(gi)*ftanh(gg);
                float hv = sigf(go)*ftanh(cv);
                p2[gm*H4 + 512 + h] = cv;     // HC c1
                p2[gm*H4 + 768 + h] = hv;     // HC h1
            }
        }
    }
}

// ---------------- persistent skip-encoder kernel ----------------
// Shared GEMM inner: A (32 x 256) resident in smem As, B streamed from global.
struct SkipSmem {
    float As[32][260];
    float Bs[2][16][64];
    float mu[32];
    float rs[32];
    int   act[32];
};

__device__ __forceinline__ void gemm_smem_pass(
    float (&acc)[4][4], const float* __restrict__ Bg, int col0,
    SkipSmem* sm, int tid, int tx, int ty)
{
    const int bk = tid >> 4;
    const int bn = (tid & 15) << 2;
    float4 rb0 = *(const float4*)&Bg[bk*H4 + col0 + bn];
    float4 rb1 = *(const float4*)&Bg[(bk+8)*H4 + col0 + bn];
    *(float4*)&sm->Bs[0][bk][bn] = rb0;
    *(float4*)&sm->Bs[0][bk+8][bn] = rb1;
    __syncthreads();
    for (int kc = 0; kc < 16; kc++) {
        const int p = kc & 1;
        if (kc+1 < 16) {
            int k0 = (kc+1) << 4;
            rb0 = *(const float4*)&Bg[(k0+bk)*H4 + col0 + bn];
            rb1 = *(const float4*)&Bg[(k0+bk+8)*H4 + col0 + bn];
        }
        #pragma unroll
        for (int kk = 0; kk < 16; kk++) {
            float4 b4 = *(const float4*)&sm->Bs[p][kk][tx<<2];
            int k = (kc<<4) + kk;
            float a0 = sm->As[(ty<<2)+0][k];
            float a1 = sm->As[(ty<<2)+1][k];
            float a2 = sm->As[(ty<<2)+2][k];
            float a3 = sm->As[(ty<<2)+3][k];
            acc[0][0]+=a0*b4.x; acc[0][1]+=a0*b4.y; acc[0][2]+=a0*b4.z; acc[0][3]+=a0*b4.w;
            acc[1][0]+=a1*b4.x; acc[1][1]+=a1*b4.y; acc[1][2]+=a1*b4.z; acc[1][3]+=a1*b4.w;
            acc[2][0]+=a2*b4.x; acc[2][1]+=a2*b4.y; acc[2][2]+=a2*b4.z; acc[2][3]+=a2*b4.w;
            acc[3][0]+=a3*b4.x; acc[3][1]+=a3*b4.y; acc[3][2]+=a3*b4.z; acc[3][3]+=a3*b4.w;
        }
        if (kc+1 < 16) {
            const int q = p ^ 1;
            *(float4*)&sm->Bs[q][bk][bn] = rb0;
            *(float4*)&sm->Bs[q][bk+8][bn] = rb1;
            __syncthreads();
        }
    }
    __syncthreads();
}

__global__ void __launch_bounds__(128) skip_persistent(
    const float* __restrict__ lns, const float* __restrict__ lnb)
{
    __shared__ SkipSmem sm;
    const int tid = threadIdx.x;
    const int tx = tid & 15, ty = tid >> 4;
    const int sr = tid >> 2;        // stats row 0..31
    const int sp = tid & 3;         // stats part 0..3

    for (int idx = 0; idx < NSTMT; idx++) {
        const int M = BATCH*(idx+1);
        const int RT = (M + 31) >> 5;
        const int NT = RT << 4;
        const int actlim = BATCH*idx;          // rows < actlim were active last step
        const int cur = idx & 1, prv = cur ^ 1;
        const float* Rc0p = d_RC0 + prv*CHAINS*HID;
        const float* Rh0p = d_RH0 + prv*CHAINS*HID;
        const float* Rc1p = d_RC1 + prv*CHAINS*HID;
        const float* Rh1p = d_RH1 + prv*CHAINS*HID;
        float* Rc0c = d_RC0 + cur*CHAINS*HID;
        float* Rh0c = d_RH0 + cur*CHAINS*HID;
        float* Rc1c = d_RC1 + cur*CHAINS*HID;
        float* Rh1c = d_RH1 + cur*CHAINS*HID;

        // ---------------- Phase A: layer-0 ----------------
        for (int t = blockIdx.x; t < NT; t += gridDim.x) {
            const int rt = t >> 4, ct = t & 15;
            const int r0 = rt << 5;
            const int col0 = ct << 6;
            // stats over prev raw state (LN params)
            {
                int gm = r0 + sr;
                bool a = (gm < actlim);
                float s = 0.f, s2 = 0.f;
                if (a) {
                    const float* src = (sp == 0 ? Rc0p : sp == 1 ? Rh0p : sp == 2 ? Rc1p : Rh1p) + gm*HID;
                    #pragma unroll 4
                    for (int k = 0; k < 64; k++) {
                        float4 v = make_float4(__ldcg(src+4*k), __ldcg(src+4*k+1),
                                               __ldcg(src+4*k+2), __ldcg(src+4*k+3));
                        s  += v.x+v.y+v.z+v.w;
                        s2 += v.x*v.x+v.y*v.y+v.z*v.z+v.w*v.w;
                    }
                }
                s  += __shfl_xor_sync(0xffffffffu, s, 1);
                s  += __shfl_xor_sync(0xffffffffu, s, 2);
                s2 += __shfl_xor_sync(0xffffffffu, s2, 1);
                s2 += __shfl_xor_sync(0xffffffffu, s2, 2);
                if (sp == 0) {
                    float mu = s * (1.f/1024.f);
                    float var = fmaxf(s2 * (1.f/1024.f) - mu*mu, 0.f);
                    sm.mu[sr] = mu;
                    sm.rs[sr] = rsqrtf(var + 1e-6f);
                    sm.act[sr] = a ? 1 : 0;
                }
            }
            __syncthreads();
            // build As = LN'd h0_prev (zero for new/out-of-range rows)
            {
                int gm = r0 + sr;
                bool a = (gm < actlim);
                float mu = sm.mu[sr], rs = sm.rs[sr];
                const float* src = Rh0p + gm*HID + sp*64;
                const float* s4 = lns + 256 + sp*64;
                const float* b4 = lnb + 256 + sp*64;
                #pragma unroll 4
                for (int k = 0; k < 64; k += 4) {
                    float4 o;
                    if (a) {
                        o.x = (__ldcg(src+k)  -mu)*rs*s4[k]  +b4[k];
                        o.y = (__ldcg(src+k+1)-mu)*rs*s4[k+1]+b4[k+1];
                        o.z = (__ldcg(src+k+2)-mu)*rs*s4[k+2]+b4[k+2];
                        o.w = (__ldcg(src+k+3)-mu)*rs*s4[k+3]+b4[k+3];
                    } else o = make_float4(0.f,0.f,0.f,0.f);
                    *(float4*)&sm.As[sr][sp*64 + k] = o;
                }
            }
            __syncthreads();
            float acc[4][4] = {};
            gemm_smem_pass(acc, d_WSKH0, col0, &sm, tid, tx, ty);
            // epilogue: + XG0, LSTM cell layer 0
            const int u = (col0 >> 2) + tx;
            #pragma unroll
            for (int i = 0; i < 4; i++) {
                int r = (ty<<2) + i;
                int gm = r0 + r;
                if (gm >= M) continue;
                float mu = sm.mu[r], rs = sm.rs[r];
                bool a = sm.act[r] != 0;
                int b = gm & 7;
                const float4 xv = *(const float4*)&d_XG0[((b*NSTMT)+idx)*H4 + (u<<2)];
                float gi = acc[i][0]+xv.x, gf = acc[i][1]+xv.y;
                float gg = acc[i][2]+xv.z, go = acc[i][3]+xv.w;
                float c0p = a ? (__ldcg(Rc0p + gm*HID + u) - mu)*rs*lns[u] + lnb[u] : 0.f;
                float cv = sigf(gf)*c0p + sigf(gi)*ftanh(gg);
                float hv = sigf(go)*ftanh(cv);
                Rc0c[gm*HID + u] = cv;
                Rh0c[gm*HID + u] = hv;
                if (ct == 0 && tx == 0) { d_MU[gm] = mu; d_RSD[gm] = rs; }
            }
            __syncthreads();
        }
        grid_barrier();

        // ---------------- Phase B: layer-1 (K=512 in two passes) ----------------
        for (int t = blockIdx.x; t < NT; t += gridDim.x) {
            const int rt = t >> 4, ct = t & 15;
            const int r0 = rt << 5;
            const int col0 = ct << 6;
            // load stats
            if (tid < 32) {
                int gm = r0 + tid;
                sm.mu[tid] = (gm < CHAINS) ? __ldcg(d_MU + gm) : 0.f;
                sm.rs[tid] = (gm < CHAINS) ? __ldcg(d_RSD + gm) : 0.f;
                sm.act[tid] = (gm < actlim) ? 1 : 0;
            }
            __syncthreads();
            // pass 0: As = raw h0 (current step)
            {
                int gm = r0 + sr;
                const float* src = Rh0c + gm*HID + sp*64;
                bool inr = (gm < M);
                #pragma unroll 4
                for (int k = 0; k < 64; k += 4) {
                    float4 o = inr ? make_float4(__ldcg(src+k), __ldcg(src+k+1),
                                                 __ldcg(src+k+2), __ldcg(src+k+3))
                                   : make_float4(0.f,0.f,0.f,0.f);
                    *(float4*)&sm.As[sr][sp*64 + k] = o;
                }
            }
            __syncthreads();
            float acc[4][4] = {};
            gemm_smem_pass(acc, d_WSK1, col0, &sm, tid, tx, ty);
            // pass 1: As = LN'd h1_prev
            {
                int gm = r0 + sr;
                bool a = sm.act[sr] != 0;
                float mu = sm.mu[sr], rs = sm.rs[sr];
                const float* src = Rh1p + gm*HID + sp*64;
                const float* s4 = lns + 768 + sp*64;
                const float* b4 = lnb + 768 + sp*64;
                #pragma unroll 4
                for (int k = 0; k < 64; k += 4) {
                    float4 o;
                    if (a) {
                        o.x = (__ldcg(src+k)  -mu)*rs*s4[k]  +b4[k];
                        o.y = (__ldcg(src+k+1)-mu)*rs*s4[k+1]+b4[k+1];
                        o.z = (__ldcg(src+k+2)-mu)*rs*s4[k+2]+b4[k+2];
                        o.w = (__ldcg(src+k+3)-mu)*rs*s4[k+3]+b4[k+3];
                    } else o = make_float4(0.f,0.f,0.f,0.f);
                    *(float4*)&sm.As[sr][sp*64 + k] = o;
                }
            }
            __syncthreads();
            gemm_smem_pass(acc, d_WSK1 + 256*H4, col0, &sm, tid, tx, ty);
            // epilogue: + bias, LSTM cell layer 1, write SKIP output
            const int u = (col0 >> 2) + tx;
            const float4 bv = *(const float4*)&d_BSK1[u<<2];
            #pragma unroll
            for (int i = 0; i < 4; i++) {
                int r = (ty<<2) + i;
                int gm = r0 + r;
                if (gm >= M) continue;
                float mu = sm.mu[r], rs = sm.rs[r];
                bool a = sm.act[r] != 0;
                float gi = acc[i][0]+bv.x, gf = acc[i][1]+bv.y;
                float gg = acc[i][2]+bv.z, go = acc[i][3]+bv.w;
                float c1p = a ? (__ldcg(Rc1p + gm*HID + u) - mu)*rs*lns[512+u] + lnb[512+u] : 0.f;
                float cv = sigf(gf)*c1p + sigf(gi)*ftanh(gg);
                float hv = sigf(go)*ftanh(cv);
                Rc1c[gm*HID + u] = cv;
                Rh1c[gm*HID + u] = hv;
                int s = gm >> 3, b = gm & 7;
                d_SKIP[((b*NNODE + s)*NNODE + (idx+1))*HID + u] = hv;
            }
            __syncthreads();
        }
        grid_barrier();
    }
}

// ---------------- main-loop kernels ----------------
__global__ void __launch_bounds__(256) attn_kernel(const float* __restrict__ w1,
                                                   const float* __restrict__ b1, int step) {
    int bn = blockIdx.x;               // b*81 + n
    int n = bn % NNODE;
    __shared__ float qsh[HID], w1sh[HID], lg[NNODE];
    int tid = threadIdx.x;
    qsh[tid]  = d_Q[bn*HID + tid];
    w1sh[tid] = w1[tid];
    __syncthreads();
    int w = tid >> 5, lane = tid & 31;
    float b1v = b1[0];
    for (int m = w; m < NNODE; m += 8) {
        const float* kr = d_KEYS + (bn*NNODE + m)*HID;
        float acc = 0.f;
        #pragma unroll 4
        for (int h = lane; h < HID; h += 32)
            acc += ftanh(qsh[h] + kr[h]) * w1sh[h];
        #pragma unroll
        for (int o = 16; o; o >>= 1) acc += __shfl_xor_sync(0xffffffffu, acc, o);
        if (lane == 0) {
            bool allowed = (step == 0) ? (m == 1)
                        : ((step == NSTEP-1) ? (m == NNODE-1)
                                             : (m > n || m == NNODE-1));
            lg[m] = allowed ? (acc + b1v) : -1e9f;
        }
    }
    __syncthreads();
    if (w == 0) {
        float mx = -1e30f;
        for (int m = lane; m < NNODE; m += 32) mx = fmaxf(mx, lg[m]);
        #pragma unroll
        for (int o = 16; o; o >>= 1) mx = fmaxf(mx, __shfl_xor_sync(0xffffffffu, mx, o));
        float sum = 0.f;
        for (int m = lane; m < NNODE; m += 32) { float e = expf(lg[m]-mx); lg[m] = e; sum += e; }
        #pragma unroll
        for (int o = 16; o; o >>= 1) sum += __shfl_xor_sync(0xffffffffu, sum, o);
        float scale = d_P[bn] / sum;
        for (int m = lane; m < NNODE; m += 32) d_T[bn*NNODE + m] = lg[m]*scale;
    }
}

__global__ void newp_kernel() {
    int b = blockIdx.x, m = threadIdx.x;
    if (m < NNODE) {
        float s = 0.f;
        for (int n = 0; n < NNODE; n++) s += d_T[(b*NNODE+n)*NNODE + m];
        d_P[b*NNODE + m] = s;
    }
}

__global__ void __launch_bounds__(256) props_kernel() {
    int bm = blockIdx.x;
    int b = bm / NNODE, m = bm % NNODE;
    __shared__ float tsh[NNODE];
    int tid = threadIdx.x;
    if (tid < NNODE) tsh[tid] = d_T[(b*NNODE+tid)*NNODE + m];
    __syncthreads();
    float inv = 1.f / (d_P[bm] + 1e-7f);
    float ax=0.f, a0=0.f, a1=0.f, a2=0.f, a3=0.f;
    for (int n = 0; n < NNODE; n++) {
        float tv = tsh[n];
        if (tv == 0.f) continue;
        const float* sr = d_SKIP + ((b*NNODE+n)*NNODE + m)*HID;
        const float* hr = d_HC + (b*NNODE+n)*H4;
        ax += tv*sr[tid];
        a0 += tv*hr[tid];      a1 += tv*hr[256+tid];
        a2 += tv*hr[512+tid];  a3 += tv*hr[768+tid];
    }
    d_XHE[bm*512 + tid]       = ax*inv;  // x_in
    d_CPR[bm*512 + tid]       = a0*inv;  // c0 prop
    d_XHE[bm*512 + 256 + tid] = a1*inv;  // h0 prop
    d_CPR[bm*512 + 256 + tid] = a2*inv;  // c1 prop
    d_XH2[bm*512 + 256 + tid] = a3*inv;  // h1 prop
}

// ---------------- output projection ----------------
__global__ void __launch_bounds__(256) out_kernel(const int* __restrict__ exit_idx,
                                                  const float* __restrict__ wo,
                                                  const float* __restrict__ bo,
                                                  float* __restrict__ out) {
    __shared__ float hex[BATCH][HID];
    int tid = threadIdx.x;
    for (int i = tid; i < BATCH*HID; i += 256) {
        int b = i >> 8, h = i & 255;
        hex[b][h] = d_HC[(b*NNODE + exit_idx[b])*H4 + 768 + h];
    }
    __syncthreads();
    int col = blockIdx.x*256 + tid;
    if (col >= VOCAB) return;
    float acc[BATCH];
    #pragma unroll
    for (int b = 0; b < BATCH; b++) acc[b] = 0.f;
    for (int h = 0; h < HID; h++) {
        float wv = wo[h*VOCAB + col];
        #pragma unroll
        for (int b = 0; b < BATCH; b++) acc[b] += hex[b][h]*wv;
    }
    float bv = bo[col];
    #pragma unroll
    for (int b = 0; b < BATCH; b++) out[b*VOCAB + col] = acc[b] + bv;
}

// ---------------- host ----------------
static inline float* sym(const void* s) {
    void* p = nullptr;
    cudaGetSymbolAddress(&p, s);
    return (float*)p;
}

template<int EPI>
static inline void launch_gemm(const float* A, const float* B, const float* bias, float* C,
                               int M, int K, int N,
                               float* p1 = 0, float* p2 = 0, float* p3 = 0) {
    dim3 g(N/64, (M+31)/32);
    gemm_epi<EPI><<<g, 128>>>(A, B, bias, C, M, K, N, p1, p2, p3);
}

extern "C" void kernel_launch(void* const* d_in, const int* in_sizes, int n_in,
                              void* d_out, int out_size) {
    const float* node_emb = (const float*)d_in[0];
    const int*   exit_idx = (const int*)  d_in[10];
    const float* st_Wx = (const float*)d_in[12];
    const float* st_b  = (const float*)d_in[14];
    const float* sk_Wx = (const float*)d_in[15];
    const float* sk_Wh = (const float*)d_in[16];
    const float* sk_b  = (const float*)d_in[17];
    const float* ln_s  = (const float*)d_in[18];
    const float* ln_b  = (const float*)d_in[19];
    const float* ex_Wx = (const float*)d_in[20];
    const float* ex_Wh = (const float*)d_in[21];
    const float* ex_b  = (const float*)d_in[22];
    const float* wk = (const float*)d_in[23];
    const float* bk = (const float*)d_in[24];
    const float* ws = (const float*)d_in[25];
    const float* bs = (const float*)d_in[26];
    const float* w1 = (const float*)d_in[27];
    const float* b1 = (const float*)d_in[28];
    const float* wo = (const float*)d_in[29];
    const float* bo = (const float*)d_in[30];
    float* out = (float*)d_out;

    float* pSTMT = sym(d_STMT);
    float* pTMPH = sym(d_TMPH);
    float* pXG0  = sym(d_XG0);
    float* pSKIP = sym(d_SKIP);
    float* pKEYS = sym(d_KEYS);
    float* pHC   = sym(d_HC);
    float* pQ    = sym(d_Q);
    float* pXHE  = sym(d_XHE);
    float* pXH2  = sym(d_XH2);
    float* pCPR  = sym(d_CPR);
    float* pWST0 = sym(d_WST0);
    float* pWST1 = sym(d_WST1);
    float* pWSKX0= sym(d_WSKX0);
    float* pWEX0 = sym(d_WEX0);
    float* pWEX1 = sym(d_WEX1);
    float* pBST0 = sym(d_BST0);
    float* pBST1 = sym(d_BST1);
    float* pBSK0 = sym(d_BSK0);
    float* pBEX0 = sym(d_BEX0);
    float* pBEX1 = sym(d_BEX1);

    const int MB = BATCH*NSTMT;  // 640

    init_kernel<<<512, 256>>>();
    build_w<<<(512*H4 + 255)/256, 256>>>(st_Wx, sk_Wx, sk_Wh, ex_Wx, ex_Wh);
    build_b<<<(H4 + 255)/256, 256>>>(st_b, sk_b, ex_b);

    // statement embedder: single LSTM step from zero state (h=0 => no Wh term)
    launch_gemm<1>(node_emb, pWST0, pBST0, nullptr, MB, HID, H4, pTMPH);
    launch_gemm<1>(pTMPH,    pWST1, pBST1, nullptr, MB, HID, H4, pSTMT);

    // xg0 = stmt @ skWx0 + skb0 (interleaved), shared by all 81 starts
    launch_gemm<0>(pSTMT, pWSKX0, pBSK0, pXG0, MB, HID, H4);

    // skip encoder: single persistent kernel over all 80 steps
    skip_persistent<<<NB, 128>>>(ln_s, ln_b);

    // keys = skip @ ws + bs
    launch_gemm<0>(pSKIP, ws, bs, pKEYS, BATCH*NNODE*NNODE, HID, HID);

    // main interpreter loop
    for (int step = 0; step < NSTEP; step++) {
        launch_gemm<0>(pHC, wk, bk, pQ, CHAINS, H4, HID);
        attn_kernel<<<CHAINS, 256>>>(w1, b1, step);
        newp_kernel<<<BATCH, 96>>>();
        props_kernel<<<CHAINS, 256>>>();
        launch_gemm<4>(pXHE, pWEX0, pBEX0, nullptr, CHAINS, 512, H4,
                       pCPR, pHC, pXH2);
        launch_gemm<5>(pXH2, pWEX1, pBEX1, nullptr, CHAINS, 512, H4,
                       pCPR, pHC, nullptr);
    }

    out_kernel<<<(VOCAB + 255)/256, 256>>>(exit_idx, wo, bo, out);
}

// round 4
// speedup vs baseline: 1.8109x; 1.8109x over previous
#include <cuda_runtime.h>
#include <cuda_bf16.h>
#include <math.h>

// Problem constants
#define BATCH 8
#define NSTMT 80
#define NNODE 81
#define HID   256
#define H4    1024
#define NSTEP 8
#define VOCAB 30000
#define CHAINS (NNODE*BATCH)   // 648

#define ASTR 40   // smem A row stride (bf16 elems), 16B-aligned rows
#define BSTR 72   // smem B row stride

// ---------------- device scratch (allocation-free) ----------------
static __device__ float d_SKIP[BATCH*NNODE*NNODE*HID];   // [b][start][pos][h]
static __device__ float d_KEYS[BATCH*NNODE*NNODE*HID];
static __device__ float d_STMT[BATCH*NSTMT*HID];
static __device__ float d_TMPH[BATCH*NSTMT*HID];
static __device__ float d_XG0 [BATCH*NSTMT*H4];          // stmt@skWx0 + skb0 (interleaved)
static __device__ float d_SC0[CHAINS*HID];  // c0 (LN'd between steps; raw inside step)
static __device__ float d_SH0[CHAINS*HID];  // h0 LN'd (GEMM A operand)
static __device__ float d_SC1[CHAINS*HID];
static __device__ float d_SH1[CHAINS*HID];
static __device__ float d_RH0[CHAINS*HID];  // raw h0 this step
static __device__ float d_RH1[CHAINS*HID];  // raw h1 this step
static __device__ float d_XH1[CHAINS*512];  // [h0_raw_new, h1_prev_LN]
static __device__ float d_HC [CHAINS*H4];   // exec state: c0,h0,c1,h1
static __device__ float d_Q  [CHAINS*HID];
static __device__ float d_T  [BATCH*NNODE*NNODE];
static __device__ float d_P  [CHAINS];
static __device__ float d_XHE[CHAINS*512];  // [x_in, h0prop]
static __device__ float d_XH2[CHAINS*512];  // [h0new, h1prop]
static __device__ float d_CPR[CHAINS*512];  // [c0prop, c1prop]
// bf16 hi/lo split weights (hi at [0], lo at [K*N]); recurrent ones gate-interleaved
static __device__ __nv_bfloat16 d_ST0w [2*HID*H4];
static __device__ __nv_bfloat16 d_ST1w [2*HID*H4];
static __device__ __nv_bfloat16 d_SKX0w[2*HID*H4];
static __device__ __nv_bfloat16 d_SKH0w[2*HID*H4];
static __device__ __nv_bfloat16 d_SK1w [2*512*H4];
static __device__ __nv_bfloat16 d_EX0w [2*512*H4];
static __device__ __nv_bfloat16 d_EX1w [2*512*H4];
static __device__ __nv_bfloat16 d_WSw  [2*HID*HID];
static __device__ __nv_bfloat16 d_WKw  [2*H4*HID];
static __device__ float d_BST0[H4], d_BST1[H4], d_BSK0[H4], d_BSK1[H4], d_BEX0[H4], d_BEX1[H4];

// ---------------- helpers ----------------
__device__ __forceinline__ float sigf(float x){ return 1.f/(1.f+__expf(-x)); }
__device__ __forceinline__ float ftanh(float x){ return 1.f - 2.f/(__expf(2.f*x)+1.f); }

__device__ __forceinline__ float block_sum(float v, float* sh) {
    int lane = threadIdx.x & 31, w = threadIdx.x >> 5;
    #pragma unroll
    for (int o = 16; o; o >>= 1) v += __shfl_xor_sync(0xffffffffu, v, o);
    __syncthreads();
    if (lane == 0) sh[w] = v;
    __syncthreads();
    return sh[0]+sh[1]+sh[2]+sh[3]+sh[4]+sh[5]+sh[6]+sh[7];
}

// split float -> bf16 hi/lo packed pair (elements 2e, 2e+1 -> one u32, low half first)
__device__ __forceinline__ unsigned pack_hl(float x0, float x1, unsigned& lo_out) {
    __nv_bfloat16 h0 = __float2bfloat16(x0);
    __nv_bfloat16 h1 = __float2bfloat16(x1);
    __nv_bfloat16 l0 = __float2bfloat16(x0 - __bfloat162float(h0));
    __nv_bfloat16 l1 = __float2bfloat16(x1 - __bfloat162float(h1));
    unsigned uh = (unsigned)__bfloat16_as_ushort(h0) | ((unsigned)__bfloat16_as_ushort(h1) << 16);
    lo_out      = (unsigned)__bfloat16_as_ushort(l0) | ((unsigned)__bfloat16_as_ushort(l1) << 16);
    return uh;
}

__device__ __forceinline__ void store_hl(__nv_bfloat16* base, int total, int i, float v) {
    __nv_bfloat16 h = __float2bfloat16(v);
    base[i] = h;
    base[total + i] = __float2bfloat16(v - __bfloat162float(h));
}

__device__ __forceinline__ void ldsm_x4(unsigned* r, const __nv_bfloat16* p) {
    unsigned addr = (unsigned)__cvta_generic_to_shared(p);
    asm volatile("ldmatrix.sync.aligned.m8n8.x4.shared.b16 {%0,%1,%2,%3}, [%4];"
        : "=r"(r[0]), "=r"(r[1]), "=r"(r[2]), "=r"(r[3]) : "r"(addr));
}
__device__ __forceinline__ void ldsm_x4_t(unsigned* r, const __nv_bfloat16* p) {
    unsigned addr = (unsigned)__cvta_generic_to_shared(p);
    asm volatile("ldmatrix.sync.aligned.m8n8.x4.trans.shared.b16 {%0,%1,%2,%3}, [%4];"
        : "=r"(r[0]), "=r"(r[1]), "=r"(r[2]), "=r"(r[3]) : "r"(addr));
}
__device__ __forceinline__ void mma_bf16(float* c, const unsigned* a, const unsigned* b) {
    asm volatile("mma.sync.aligned.m16n8k16.row.col.f32.bf16.bf16.f32 "
        "{%0,%1,%2,%3}, {%4,%5,%6,%7}, {%8,%9}, {%0,%1,%2,%3};"
        : "+f"(c[0]), "+f"(c[1]), "+f"(c[2]), "+f"(c[3])
        : "r"(a[0]), "r"(a[1]), "r"(a[2]), "r"(a[3]), "r"(b[0]), "r"(b[1]));
}

// ---------------- init / weight prep ----------------
__global__ void init_kernel() {
    int stride = gridDim.x * blockDim.x;
    int gid = blockIdx.x * blockDim.x + threadIdx.x;
    for (int i = gid; i < BATCH*NNODE*NNODE*HID; i += stride) d_SKIP[i] = 0.f;
    for (int i = gid; i < CHAINS*HID; i += stride) {
        d_SC0[i]=0.f; d_SH0[i]=0.f; d_SC1[i]=0.f; d_SH1[i]=0.f;
    }
    for (int i = gid; i < CHAINS*512; i += stride) d_XH1[i] = 0.f;
    for (int i = gid; i < CHAINS*H4; i += stride) d_HC[i] = 0.f;
    for (int i = gid; i < CHAINS; i += stride) d_P[i] = (i % NNODE == 0) ? 1.f : 0.f;
}

__global__ void build_w(const float* __restrict__ stWx, const float* __restrict__ skWx,
                        const float* __restrict__ skWh, const float* __restrict__ exWx,
                        const float* __restrict__ exWh, const float* __restrict__ wk,
                        const float* __restrict__ ws) {
    int i = blockIdx.x*256 + threadIdx.x;
    if (i >= 512*H4) return;
    int k = i >> 10, n = i & 1023;
    int h = n >> 2, g = n & 3;
    int sc = h + 256*g;                 // source (non-interleaved) column
    const int L1 = 256*H4;
    float v;
    v = (k < 256) ? skWx[L1 + k*H4 + sc] : skWh[L1 + (k-256)*H4 + sc];
    store_hl(d_SK1w, 512*H4, i, v);
    v = (k < 256) ? exWx[k*H4 + sc]      : exWh[(k-256)*H4 + sc];
    store_hl(d_EX0w, 512*H4, i, v);
    v = (k < 256) ? exWx[L1 + k*H4 + sc] : exWh[L1 + (k-256)*H4 + sc];
    store_hl(d_EX1w, 512*H4, i, v);
    if (k < 256) {
        int j = k*H4 + n;
        store_hl(d_ST0w,  HID*H4, j, stWx[k*H4 + sc]);
        store_hl(d_ST1w,  HID*H4, j, stWx[L1 + k*H4 + sc]);
        store_hl(d_SKX0w, HID*H4, j, skWx[k*H4 + sc]);
        store_hl(d_SKH0w, HID*H4, j, skWh[k*H4 + sc]);
    }
    if (i < H4*HID)  store_hl(d_WKw, H4*HID,  i, wk[i]);
    if (i < HID*HID) store_hl(d_WSw, HID*HID, i, ws[i]);
}

__global__ void build_b(const float* __restrict__ st_b, const float* __restrict__ sk_b,
                        const float* __restrict__ ex_b) {
    int i = blockIdx.x*256 + threadIdx.x;
    if (i >= H4) return;
    int h = i >> 2, g = i & 3;
    int sc = h + 256*g;
    d_BST0[i] = st_b[sc];       d_BST1[i] = st_b[H4 + sc];
    d_BSK0[i] = sk_b[sc];       d_BSK1[i] = sk_b[H4 + sc];
    d_BEX0[i] = ex_b[sc];       d_BEX1[i] = ex_b[H4 + sc];
}

// ---------------- tensor-core GEMM (bf16 hi/lo split) + fused LSTM epilogues --------
// C[M,N] = A[M,K] @ B[K,N]; 64x64 block tile, 128 threads (4 warps, 32x32 each).
// A fp32 (split on the fly); B pre-split bf16: hi at Bh_g, lo at Bh_g + K*N.
// EPI: 0 plain(+col bias), 1 stmt zero-carry, 2 skip L0, 3 skip L1, 4 exec L0, 5 exec L1
template<int EPI>
__global__ void __launch_bounds__(128) gemm_mma(
    const float* __restrict__ A, const __nv_bfloat16* __restrict__ Bh_g,
    const float* __restrict__ bias, float* __restrict__ C,
    int M, int K, int N,
    float* __restrict__ p1, float* __restrict__ p2, float* __restrict__ p3,
    const float* __restrict__ p4, int idx)
{
    const __nv_bfloat16* Bl_g = Bh_g + (size_t)K*N;
    __shared__ __align__(16) __nv_bfloat16 sAh[64*ASTR];
    __shared__ __align__(16) __nv_bfloat16 sAl[64*ASTR];
    __shared__ __align__(16) __nv_bfloat16 sBh[32*BSTR];
    __shared__ __align__(16) __nv_bfloat16 sBl[32*BSTR];

    const int tid  = threadIdx.x;
    const int lane = tid & 31;
    const int wid  = tid >> 5;
    const int wr   = wid >> 1;          // warp row 0..1
    const int wc   = wid & 1;           // warp col 0..1
    const int row0 = blockIdx.y << 6;
    const int col0 = blockIdx.x << 6;

    // staging assignments
    const int arow = tid >> 1;                 // A: 64 rows x 32 k; thread -> (row, 16-k half)
    const int akq  = (tid & 1) << 4;
    const bool aval = (row0 + arow) < M;
    const float* Ag = A + (size_t)(row0 + arow)*K + akq;
    const int seg0 = tid << 1;                 // B: 256 segs of 8 bf16

    float acc[2][4][4];
    #pragma unroll
    for (int a = 0; a < 2; a++)
        #pragma unroll
        for (int b = 0; b < 4; b++)
            #pragma unroll
            for (int cc = 0; cc < 4; cc++) acc[a][b][cc] = 0.f;

    const int NC = K >> 5;
    for (int cidx = 0; cidx < NC; cidx++) {
        const int k0 = cidx << 5;
        // global loads
        float av[16];
        #pragma unroll
        for (int j = 0; j < 4; j++) {
            float4 f = aval ? *(const float4*)(Ag + k0 + 4*j) : make_float4(0.f,0.f,0.f,0.f);
            av[4*j]=f.x; av[4*j+1]=f.y; av[4*j+2]=f.z; av[4*j+3]=f.w;
        }
        uint4 bvh[2], bvl[2];
        #pragma unroll
        for (int s = 0; s < 2; s++) {
            int seg = seg0 + s;
            int krow = seg >> 3, nc = (seg & 7) << 3;
            size_t off = (size_t)(k0 + krow)*N + col0 + nc;
            bvh[s] = *(const uint4*)(Bh_g + off);
            bvl[s] = *(const uint4*)(Bl_g + off);
        }
        __syncthreads();   // previous compute done reading smem
        #pragma unroll
        for (int e = 0; e < 8; e++) {
            unsigned ul;
            unsigned uh = pack_hl(av[2*e], av[2*e+1], ul);
            *reinterpret_cast<unsigned*>(&sAh[arow*ASTR + akq + 2*e]) = uh;
            *reinterpret_cast<unsigned*>(&sAl[arow*ASTR + akq + 2*e]) = ul;
        }
        #pragma unroll
        for (int s = 0; s < 2; s++) {
            int seg = seg0 + s;
            int krow = seg >> 3, nc = (seg & 7) << 3;
            *reinterpret_cast<uint4*>(&sBh[krow*BSTR + nc]) = bvh[s];
            *reinterpret_cast<uint4*>(&sBl[krow*BSTR + nc]) = bvl[s];
        }
        __syncthreads();
        // compute: two k16 halves
        #pragma unroll
        for (int kk = 0; kk < 2; kk++) {
            unsigned ah[2][4], al[2][4], bh[2][4], bl[2][4];
            const int kc = (kk << 4) + ((lane >> 4) << 3);
            #pragma unroll
            for (int mi = 0; mi < 2; mi++) {
                int r = wr*32 + mi*16 + (lane & 15);
                ldsm_x4(ah[mi], &sAh[r*ASTR + kc]);
                ldsm_x4(al[mi], &sAl[r*ASTR + kc]);
            }
            const int kr = (kk << 4) + (lane & 15);
            #pragma unroll
            for (int g2 = 0; g2 < 2; g2++) {
                int nc = wc*32 + g2*16 + ((lane >> 4) << 3);
                ldsm_x4_t(bh[g2], &sBh[kr*BSTR + nc]);
                ldsm_x4_t(bl[g2], &sBl[kr*BSTR + nc]);
            }
            #pragma unroll
            for (int mi = 0; mi < 2; mi++)
                #pragma unroll
                for (int nf = 0; nf < 4; nf++) {
                    const unsigned* pbh = &bh[nf>>1][(nf&1)<<1];
                    const unsigned* pbl = &bl[nf>>1][(nf&1)<<1];
                    mma_bf16(acc[mi][nf], ah[mi], pbh);
                    mma_bf16(acc[mi][nf], al[mi], pbh);
                    mma_bf16(acc[mi][nf], ah[mi], pbl);
                }
        }
    }

    // ---------------- epilogue ----------------
    #pragma unroll
    for (int mi = 0; mi < 2; mi++) {
        int gm0 = row0 + wr*32 + mi*16 + (lane >> 2);
        #pragma unroll
        for (int nf = 0; nf < 4; nf++) {
            float v0 = acc[mi][nf][0], v1 = acc[mi][nf][1];
            float v2 = acc[mi][nf][2], v3 = acc[mi][nf][3];
            int colb = col0 + wc*32 + nf*8 + ((lane & 3) << 1);
            if (EPI == 0) {
                float b0 = bias ? bias[colb] : 0.f;
                float b1 = bias ? bias[colb+1] : 0.f;
                if (gm0 < M) {
                    float2 o = make_float2(v0+b0, v1+b1);
                    *(float2*)&C[(size_t)gm0*N + colb] = o;
                }
                if (gm0+8 < M) {
                    float2 o = make_float2(v2+b0, v3+b1);
                    *(float2*)&C[(size_t)(gm0+8)*N + colb] = o;
                }
            } else {
                float s0 = __shfl_xor_sync(0xffffffffu, v0, 1);
                float s1 = __shfl_xor_sync(0xffffffffu, v1, 1);
                float s2 = __shfl_xor_sync(0xffffffffu, v2, 1);
                float s3 = __shfl_xor_sync(0xffffffffu, v3, 1);
                if (!(lane & 1)) {
                    int u = colb >> 2;
                    float4 bv = bias ? *(const float4*)&bias[u<<2]
                                     : make_float4(0.f,0.f,0.f,0.f);
                    #pragma unroll
                    for (int rr = 0; rr < 2; rr++) {
                        int gm = gm0 + rr*8;
                        if (gm >= M) continue;
                        float gi = (rr ? v2 : v0) + bv.x;
                        float gf = (rr ? v3 : v1) + bv.y;
                        float gg = (rr ? s2 : s0) + bv.z;
                        float go = (rr ? s3 : s1) + bv.w;
                        if (EPI == 2) {
                            const float4 xv = *(const float4*)&p4[((gm & 7)*NSTMT + idx)*H4 + (u<<2)];
                            gi += xv.x; gf += xv.y; gg += xv.z; go += xv.w;
                        }
                        if (EPI == 1) {
                            float cv = sigf(gi)*ftanh(gg);
                            p1[gm*HID + u] = sigf(go)*ftanh(cv);
                        } else if (EPI == 2) {
                            float cp = p1[gm*HID + u];
                            float cv = sigf(gf)*cp + sigf(gi)*ftanh(gg);
                            float hv = sigf(go)*ftanh(cv);
                            p1[gm*HID + u] = cv;       // raw c0
                            p2[gm*HID + u] = hv;       // raw h0
                            p3[gm*512 + u] = hv;       // XH1 lower half
                        } else if (EPI == 3) {
                            float cp = p1[gm*HID + u];
                            float cv = sigf(gf)*cp + sigf(gi)*ftanh(gg);
                            float hv = sigf(go)*ftanh(cv);
                            p1[gm*HID + u] = cv;       // raw c1
                            p2[gm*HID + u] = hv;       // raw h1
                            int s = gm >> 3, b = gm & 7;
                            p3[((b*NNODE + s)*NNODE + (idx+1))*HID + u] = hv;
                        } else if (EPI == 4) {
                            float cp = p1[gm*512 + u];
                            float cv = sigf(gf)*cp + sigf(gi)*ftanh(gg);
                            float hv = sigf(go)*ftanh(cv);
                            p2[gm*H4 + u]       = cv;
                            p2[gm*H4 + HID + u] = hv;
                            p3[gm*512 + u]      = hv;
                        } else {
                            float cp = p1[gm*512 + HID + u];
                            float cv = sigf(gf)*cp + sigf(gi)*ftanh(gg);
                            float hv = sigf(go)*ftanh(cv);
                            p2[gm*H4 + 512 + u] = cv;
                            p2[gm*H4 + 768 + u] = hv;
                        }
                    }
                }
            }
        }
    }
}

// ---------------- LayerNorm over concat(c0,h0,c1,h1), writes next-step operands ------
__global__ void __launch_bounds__(256) ln_kernel(const float* __restrict__ lns,
                                                 const float* __restrict__ lnb) {
    __shared__ float sh[8];
    int c = blockIdx.x, j = threadIdx.x;
    float v0 = d_SC0[c*HID+j];   // raw c0
    float v1 = d_RH0[c*HID+j];   // raw h0
    float v2 = d_SC1[c*HID+j];   // raw c1
    float v3 = d_RH1[c*HID+j];   // raw h1
    float mu = block_sum(v0+v1+v2+v3, sh) * (1.f/1024.f);
    float e0 = v0-mu, e1 = v1-mu, e2 = v2-mu, e3 = v3-mu;
    float var = block_sum(e0*e0+e1*e1+e2*e2+e3*e3, sh) * (1.f/1024.f);
    float rs = rsqrtf(var + 1e-6f);
    d_SC0[c*HID+j] = e0*rs*lns[j]       + lnb[j];
    d_SH0[c*HID+j] = e1*rs*lns[256+j]   + lnb[256+j];
    d_SC1[c*HID+j] = e2*rs*lns[512+j]   + lnb[512+j];
    float h1 =        e3*rs*lns[768+j]  + lnb[768+j];
    d_SH1[c*HID+j] = h1;
    d_XH1[c*512 + 256 + j] = h1;
}

// ---------------- main-loop kernels ----------------
__global__ void __launch_bounds__(256) attn_kernel(const float* __restrict__ w1,
                                                   const float* __restrict__ b1, int step) {
    int bn = blockIdx.x;               // b*81 + n
    int n = bn % NNODE;
    __shared__ float qsh[HID], w1sh[HID], lg[NNODE];
    int tid = threadIdx.x;
    qsh[tid]  = d_Q[bn*HID + tid];
    w1sh[tid] = w1[tid];
    __syncthreads();
    int w = tid >> 5, lane = tid & 31;
    float b1v = b1[0];
    for (int m = w; m < NNODE; m += 8) {
        const float* kr = d_KEYS + (bn*NNODE + m)*HID;
        float acc = 0.f;
        #pragma unroll 4
        for (int h = lane; h < HID; h += 32)
            acc += ftanh(qsh[h] + kr[h]) * w1sh[h];
        #pragma unroll
        for (int o = 16; o; o >>= 1) acc += __shfl_xor_sync(0xffffffffu, acc, o);
        if (lane == 0) {
            bool allowed = (step == 0) ? (m == 1)
                        : ((step == NSTEP-1) ? (m == NNODE-1)
                                             : (m > n || m == NNODE-1));
            lg[m] = allowed ? (acc + b1v) : -1e9f;
        }
    }
    __syncthreads();
    if (w == 0) {
        float mx = -1e30f;
        for (int m = lane; m < NNODE; m += 32) mx = fmaxf(mx, lg[m]);
        #pragma unroll
        for (int o = 16; o; o >>= 1) mx = fmaxf(mx, __shfl_xor_sync(0xffffffffu, mx, o));
        float sum = 0.f;
        for (int m = lane; m < NNODE; m += 32) { float e = expf(lg[m]-mx); lg[m] = e; sum += e; }
        #pragma unroll
        for (int o = 16; o; o >>= 1) sum += __shfl_xor_sync(0xffffffffu, sum, o);
        float scale = d_P[bn] / sum;
        for (int m = lane; m < NNODE; m += 32) d_T[bn*NNODE + m] = lg[m]*scale;
    }
}

__global__ void newp_kernel() {
    int b = blockIdx.x, m = threadIdx.x;
    if (m < NNODE) {
        float s = 0.f;
        for (int n = 0; n < NNODE; n++) s += d_T[(b*NNODE+n)*NNODE + m];
        d_P[b*NNODE + m] = s;
    }
}

__global__ void __launch_bounds__(256) props_kernel() {
    int bm = blockIdx.x;
    int b = bm / NNODE, m = bm % NNODE;
    __shared__ float tsh[NNODE];
    int tid = threadIdx.x;
    if (tid < NNODE) tsh[tid] = d_T[(b*NNODE+tid)*NNODE + m];
    __syncthreads();
    float inv = 1.f / (d_P[bm] + 1e-7f);
    float ax=0.f, a0=0.f, a1=0.f, a2=0.f, a3=0.f;
    for (int n = 0; n < NNODE; n++) {
        float tv = tsh[n];
        if (tv == 0.f) continue;
        const float* sr = d_SKIP + ((b*NNODE+n)*NNODE + m)*HID;
        const float* hr = d_HC + (b*NNODE+n)*H4;
        ax += tv*sr[tid];
        a0 += tv*hr[tid];      a1 += tv*hr[256+tid];
        a2 += tv*hr[512+tid];  a3 += tv*hr[768+tid];
    }
    d_XHE[bm*512 + tid]       = ax*inv;  // x_in
    d_CPR[bm*512 + tid]       = a0*inv;  // c0 prop
    d_XHE[bm*512 + 256 + tid] = a1*inv;  // h0 prop
    d_CPR[bm*512 + 256 + tid] = a2*inv;  // c1 prop
    d_XH2[bm*512 + 256 + tid] = a3*inv;  // h1 prop
}

// ---------------- output projection ----------------
__global__ void __launch_bounds__(256) out_kernel(const int* __restrict__ exit_idx,
                                                  const float* __restrict__ wo,
                                                  const float* __restrict__ bo,
                                                  float* __restrict__ out) {
    __shared__ float hex[BATCH][HID];
    int tid = threadIdx.x;
    for (int i = tid; i < BATCH*HID; i += 256) {
        int b = i >> 8, h = i & 255;
        hex[b][h] = d_HC[(b*NNODE + exit_idx[b])*H4 + 768 + h];
    }
    __syncthreads();
    int col = blockIdx.x*256 + tid;
    if (col >= VOCAB) return;
    float acc[BATCH];
    #pragma unroll
    for (int b = 0; b < BATCH; b++) acc[b] = 0.f;
    for (int h = 0; h < HID; h++) {
        float wv = wo[h*VOCAB + col];
        #pragma unroll
        for (int b = 0; b < BATCH; b++) acc[b] += hex[b][h]*wv;
    }
    float bv = bo[col];
    #pragma unroll
    for (int b = 0; b < BATCH; b++) out[b*VOCAB + col] = acc[b] + bv;
}

// ---------------- host ----------------
static inline float* sym(const void* s) {
    void* p = nullptr;
    cudaGetSymbolAddress(&p, s);
    return (float*)p;
}
static inline __nv_bfloat16* symb(const void* s) {
    void* p = nullptr;
    cudaGetSymbolAddress(&p, s);
    return (__nv_bfloat16*)p;
}

template<int EPI>
static inline void launch_gemm(const float* A, const __nv_bfloat16* Bhl,
                               const float* bias, float* C,
                               int M, int K, int N,
                               float* p1 = 0, float* p2 = 0, float* p3 = 0,
                               const float* p4 = 0, int idx = 0) {
    dim3 g(N >> 6, (M + 63) >> 6);
    gemm_mma<EPI><<<g, 128>>>(A, Bhl, bias, C, M, K, N, p1, p2, p3, p4, idx);
}

extern "C" void kernel_launch(void* const* d_in, const int* in_sizes, int n_in,
                              void* d_out, int out_size) {
    const float* node_emb = (const float*)d_in[0];
    const int*   exit_idx = (const int*)  d_in[10];
    const float* st_Wx = (const float*)d_in[12];
    const float* st_b  = (const float*)d_in[14];
    const float* sk_Wx = (const float*)d_in[15];
    const float* sk_Wh = (const float*)d_in[16];
    const float* sk_b  = (const float*)d_in[17];
    const float* ln_s  = (const float*)d_in[18];
    const float* ln_b  = (const float*)d_in[19];
    const float* ex_Wx = (const float*)d_in[20];
    const float* ex_Wh = (const float*)d_in[21];
    const float* ex_b  = (const float*)d_in[22];
    const float* wk = (const float*)d_in[23];
    const float* bk = (const float*)d_in[24];
    const float* ws = (const float*)d_in[25];
    const float* bs = (const float*)d_in[26];
    const float* w1 = (const float*)d_in[27];
    const float* b1 = (const float*)d_in[28];
    const float* wo = (const float*)d_in[29];
    const float* bo = (const float*)d_in[30];
    float* out = (float*)d_out;

    float* pSTMT = sym(d_STMT);
    float* pTMPH = sym(d_TMPH);
    float* pXG0  = sym(d_XG0);
    float* pSKIP = sym(d_SKIP);
    float* pKEYS = sym(d_KEYS);
    float* pSC0  = sym(d_SC0);
    float* pSH0  = sym(d_SH0);
    float* pSC1  = sym(d_SC1);
    float* pRH0  = sym(d_RH0);
    float* pRH1  = sym(d_RH1);
    float* pXH1  = sym(d_XH1);
    float* pHC   = sym(d_HC);
    float* pQ    = sym(d_Q);
    float* pXHE  = sym(d_XHE);
    float* pXH2  = sym(d_XH2);
    float* pCPR  = sym(d_CPR);
    __nv_bfloat16* pST0w  = symb(d_ST0w);
    __nv_bfloat16* pST1w  = symb(d_ST1w);
    __nv_bfloat16* pSKX0w = symb(d_SKX0w);
    __nv_bfloat16* pSKH0w = symb(d_SKH0w);
    __nv_bfloat16* pSK1w  = symb(d_SK1w);
    __nv_bfloat16* pEX0w  = symb(d_EX0w);
    __nv_bfloat16* pEX1w  = symb(d_EX1w);
    __nv_bfloat16* pWSw   = symb(d_WSw);
    __nv_bfloat16* pWKw   = symb(d_WKw);
    float* pBST0 = sym(d_BST0);
    float* pBST1 = sym(d_BST1);
    float* pBSK0 = sym(d_BSK0);
    float* pBSK1 = sym(d_BSK1);
    float* pBEX0 = sym(d_BEX0);
    float* pBEX1 = sym(d_BEX1);

    const int MB = BATCH*NSTMT;  // 640

    init_kernel<<<512, 256>>>();
    build_w<<<(512*H4 + 255)/256, 256>>>(st_Wx, sk_Wx, sk_Wh, ex_Wx, ex_Wh, wk, ws);
    build_b<<<(H4 + 255)/256, 256>>>(st_b, sk_b, ex_b);

    // statement embedder: single LSTM step from zero state (h=0 => no Wh term)
    launch_gemm<1>(node_emb, pST0w, pBST0, nullptr, MB, HID, H4, pTMPH);
    launch_gemm<1>(pTMPH,    pST1w, pBST1, nullptr, MB, HID, H4, pSTMT);

    // xg0 = stmt @ skWx0 + skb0 (interleaved), shared by all 81 starts
    launch_gemm<0>(pSTMT, pSKX0w, pBSK0, pXG0, MB, HID, H4);

    // skip encoder: 80 steps over growing prefix of chains (s-major ordering)
    for (int idx = 0; idx < NSTMT; idx++) {
        int M = BATCH*(idx+1);
        launch_gemm<2>(pSH0, pSKH0w, nullptr, nullptr, M, HID, H4,
                       pSC0, pRH0, pXH1, pXG0, idx);
        launch_gemm<3>(pXH1, pSK1w, pBSK1, nullptr, M, 512, H4,
                       pSC1, pRH1, pSKIP, nullptr, idx);
        ln_kernel<<<M, 256>>>(ln_s, ln_b);
    }

    // keys = skip @ ws + bs
    launch_gemm<0>(pSKIP, pWSw, bs, pKEYS, BATCH*NNODE*NNODE, HID, HID);

    // main interpreter loop
    for (int step = 0; step < NSTEP; step++) {
        launch_gemm<0>(pHC, pWKw, bk, pQ, CHAINS, H4, HID);
        attn_kernel<<<CHAINS, 256>>>(w1, b1, step);
        newp_kernel<<<BATCH, 96>>>();
        props_kernel<<<CHAINS, 256>>>();
        launch_gemm<4>(pXHE, pEX0w, pBEX0, nullptr, CHAINS, 512, H4,
                       pCPR, pHC, pXH2);
        launch_gemm<5>(pXH2, pEX1w, pBEX1, nullptr, CHAINS, 512, H4,
                       pCPR, pHC, nullptr);
    }

    out_kernel<<<(VOCAB + 255)/256, 256>>>(exit_idx, wo, bo, out);
}

// round 5
// speedup vs baseline: 2.1410x; 1.1823x over previous
#include <cuda_runtime.h>
#include <cuda_bf16.h>
#include <math.h>

// Problem constants
#define BATCH 8
#define NSTMT 80
#define NNODE 81
#define HID   256
#define H4    1024
#define NSTEP 8
#define VOCAB 30000
#define CHAINS (NNODE*BATCH)   // 648

#define ASTR 40   // mma smem A row stride (bf16)
#define BSTR 72   // mma smem B row stride

// ---------------- device scratch (allocation-free) ----------------
static __device__ float d_SKIP[BATCH*NNODE*NNODE*HID];   // [b][start][pos][h]
static __device__ float d_KEYS[BATCH*NNODE*NNODE*HID];
static __device__ float d_STMT[BATCH*NSTMT*HID];
static __device__ float d_TMPH[BATCH*NSTMT*HID];
static __device__ float d_XG0 [BATCH*NSTMT*H4];          // stmt@skWx0 + skb0 (interleaved)
// ping-pong raw skip-LSTM state (no LN'd copies kept)
static __device__ float d_RC0[2*CHAINS*HID];
static __device__ float d_RH0[2*CHAINS*HID];
static __device__ float d_RC1[2*CHAINS*HID];
static __device__ float d_RH1[2*CHAINS*HID];
// deterministic per-(row, col-tile) partial sums of raw concat state: (sum, sumsq)
static __device__ float2 d_PSA[2][CHAINS][16];   // from skip1 (c0,h0 parts)
static __device__ float2 d_PSB[2][CHAINS][16];   // from skip2 (c1,h1 parts)
static __device__ float d_HC [CHAINS*H4];   // exec state: c0,h0,c1,h1
static __device__ float d_Q  [CHAINS*HID];
static __device__ float d_T  [BATCH*NNODE*NNODE];
static __device__ float d_P  [CHAINS];
static __device__ float d_XHE[CHAINS*512];  // [x_in, h0prop]
static __device__ float d_XH2[CHAINS*512];  // [h0new, h1prop]
static __device__ float d_CPR[CHAINS*512];  // [c0prop, c1prop]
// fp32 interleaved weights (col' = 4h + gate)
static __device__ float d_ST0f [HID*H4];
static __device__ float d_ST1f [HID*H4];
static __device__ float d_SKX0f[HID*H4];
static __device__ float d_SKH0f[HID*H4];
static __device__ float d_SK1f [512*H4];   // [skWx1; skWh1]
static __device__ float d_EX0f [512*H4];   // [exWx0; exWh0]
static __device__ float d_EX1f [512*H4];   // [exWx1; exWh1]
// bf16 hi/lo split for the big keys GEMM only
static __device__ __nv_bfloat16 d_WSw[2*HID*HID];
static __device__ float d_BST0[H4], d_BST1[H4], d_BSK0[H4], d_BSK1[H4], d_BEX0[H4], d_BEX1[H4];

// ---------------- helpers ----------------
__device__ __forceinline__ float sigf(float x){ return 1.f/(1.f+__expf(-x)); }
__device__ __forceinline__ float ftanh(float x){ return 1.f - 2.f/(__expf(2.f*x)+1.f); }

__device__ __forceinline__ void store_hl(__nv_bfloat16* base, int total, int i, float v) {
    __nv_bfloat16 h = __float2bfloat16(v);
    base[i] = h;
    base[total + i] = __float2bfloat16(v - __bfloat162float(h));
}
__device__ __forceinline__ unsigned pack_hl(float x0, float x1, unsigned& lo_out) {
    __nv_bfloat16 h0 = __float2bfloat16(x0);
    __nv_bfloat16 h1 = __float2bfloat16(x1);
    __nv_bfloat16 l0 = __float2bfloat16(x0 - __bfloat162float(h0));
    __nv_bfloat16 l1 = __float2bfloat16(x1 - __bfloat162float(h1));
    unsigned uh = (unsigned)__bfloat16_as_ushort(h0) | ((unsigned)__bfloat16_as_ushort(h1) << 16);
    lo_out      = (unsigned)__bfloat16_as_ushort(l0) | ((unsigned)__bfloat16_as_ushort(l1) << 16);
    return uh;
}
__device__ __forceinline__ void ldsm_x4(unsigned* r, const __nv_bfloat16* p) {
    unsigned addr = (unsigned)__cvta_generic_to_shared(p);
    asm volatile("ldmatrix.sync.aligned.m8n8.x4.shared.b16 {%0,%1,%2,%3}, [%4];"
        : "=r"(r[0]), "=r"(r[1]), "=r"(r[2]), "=r"(r[3]) : "r"(addr));
}
__device__ __forceinline__ void ldsm_x4_t(unsigned* r, const __nv_bfloat16* p) {
    unsigned addr = (unsigned)__cvta_generic_to_shared(p);
    asm volatile("ldmatrix.sync.aligned.m8n8.x4.trans.shared.b16 {%0,%1,%2,%3}, [%4];"
        : "=r"(r[0]), "=r"(r[1]), "=r"(r[2]), "=r"(r[3]) : "r"(addr));
}
__device__ __forceinline__ void mma_bf16(float* c, const unsigned* a, const unsigned* b) {
    asm volatile("mma.sync.aligned.m16n8k16.row.col.f32.bf16.bf16.f32 "
        "{%0,%1,%2,%3}, {%4,%5,%6,%7}, {%8,%9}, {%0,%1,%2,%3};"
        : "+f"(c[0]), "+f"(c[1]), "+f"(c[2]), "+f"(c[3])
        : "r"(a[0]), "r"(a[1]), "r"(a[2]), "r"(a[3]), "r"(b[0]), "r"(b[1]));
}

// ---------------- init / weight prep ----------------
__global__ void init_kernel() {
    int stride = gridDim.x * blockDim.x;
    int gid = blockIdx.x * blockDim.x + threadIdx.x;
    for (int i = gid; i < BATCH*NNODE*NNODE*HID; i += stride) d_SKIP[i] = 0.f;
    for (int i = gid; i < CHAINS*H4; i += stride) d_HC[i] = 0.f;
    for (int i = gid; i < CHAINS; i += stride) d_P[i] = (i % NNODE == 0) ? 1.f : 0.f;
}

__global__ void build_w(const float* __restrict__ stWx, const float* __restrict__ skWx,
                        const float* __restrict__ skWh, const float* __restrict__ exWx,
                        const float* __restrict__ exWh, const float* __restrict__ ws) {
    int i = blockIdx.x*256 + threadIdx.x;
    if (i >= 512*H4) return;
    int k = i >> 10, n = i & 1023;
    int h = n >> 2, g = n & 3;
    int sc = h + 256*g;                 // source (non-interleaved) column
    const int L1 = 256*H4;
    d_SK1f[i] = (k < 256) ? skWx[L1 + k*H4 + sc] : skWh[L1 + (k-256)*H4 + sc];
    d_EX0f[i] = (k < 256) ? exWx[k*H4 + sc]      : exWh[(k-256)*H4 + sc];
    d_EX1f[i] = (k < 256) ? exWx[L1 + k*H4 + sc] : exWh[L1 + (k-256)*H4 + sc];
    if (k < 256) {
        int j = k*H4 + n;
        d_ST0f[j]  = stWx[k*H4 + sc];
        d_ST1f[j]  = stWx[L1 + k*H4 + sc];
        d_SKX0f[j] = skWx[k*H4 + sc];
        d_SKH0f[j] = skWh[k*H4 + sc];
    }
    if (i < HID*HID) store_hl(d_WSw, HID*HID, i, ws[i]);
}

__global__ void build_b(const float* __restrict__ st_b, const float* __restrict__ sk_b,
                        const float* __restrict__ ex_b) {
    int i = blockIdx.x*256 + threadIdx.x;
    if (i >= H4) return;
    int h = i >> 2, g = i & 3;
    int sc = h + 256*g;
    d_BST0[i] = st_b[sc];       d_BST1[i] = st_b[H4 + sc];
    d_BSK0[i] = sk_b[sc];       d_BSK1[i] = sk_b[H4 + sc];
    d_BEX0[i] = ex_b[sc];       d_BEX1[i] = ex_b[H4 + sc];
}

// ---------------- fp32 SIMT GEMM + fused LSTM epilogues ----------------
// C[M,N] = A[M,K] @ B[K,N]; 32x64 tile, 128 threads, 4x4/thread, double-buffered.
// EPI: 0 plain(+col bias), 1 stmt zero-carry cell, 4 exec L0, 5 exec L1
template<int EPI>
__global__ void __launch_bounds__(128) gemm_epi(
    const float* __restrict__ A, const float* __restrict__ B,
    const float* __restrict__ bias, float* __restrict__ C,
    int M, int K, int N,
    float* __restrict__ p1, float* __restrict__ p2, float* __restrict__ p3)
{
    __shared__ float As[2][16][36];
    __shared__ float Bs[2][16][64];
    const int tid = threadIdx.x;
    const int tx = tid & 15, ty = tid >> 4;
    const int row0 = blockIdx.y * 32;
    const int col0 = blockIdx.x * 64;
    const int T = K >> 4;
    const int am = tid >> 2;
    const int ak = (tid & 3) << 2;
    const int bk = tid >> 4;
    const int bn = (tid & 15) << 2;
    const int gmA = row0 + am;
    float acc[4][4] = {};
    float4 ra, rb0, rb1;
    ra = (gmA < M) ? *(const float4*)&A[(size_t)gmA*K + ak] : make_float4(0.f,0.f,0.f,0.f);
    rb0 = *(const float4*)&B[(size_t)bk*N + col0 + bn];
    rb1 = *(const float4*)&B[(size_t)(bk+8)*N + col0 + bn];
    As[0][ak][am]=ra.x; As[0][ak+1][am]=ra.y; As[0][ak+2][am]=ra.z; As[0][ak+3][am]=ra.w;
    *(float4*)&Bs[0][bk][bn] = rb0;
    *(float4*)&Bs[0][bk+8][bn] = rb1;
    __syncthreads();
    for (int t = 0; t < T; t++) {
        const int p = t & 1;
        if (t+1 < T) {
            int k0 = (t+1) << 4;
            ra = (gmA < M) ? *(const float4*)&A[(size_t)gmA*K + k0 + ak] : make_float4(0.f,0.f,0.f,0.f);
            rb0 = *(const float4*)&B[(size_t)(k0+bk)*N + col0 + bn];
            rb1 = *(const float4*)&B[(size_t)(k0+bk+8)*N + col0 + bn];
        }
        #pragma unroll
        for (int kk = 0; kk < 16; kk++) {
            float4 b4 = *(const float4*)&Bs[p][kk][tx<<2];
            float4 a4 = *(const float4*)&As[p][kk][ty<<2];
            acc[0][0]+=a4.x*b4.x; acc[0][1]+=a4.x*b4.y; acc[0][2]+=a4.x*b4.z; acc[0][3]+=a4.x*b4.w;
            acc[1][0]+=a4.y*b4.x; acc[1][1]+=a4.y*b4.y; acc[1][2]+=a4.y*b4.z; acc[1][3]+=a4.y*b4.w;
            acc[2][0]+=a4.z*b4.x; acc[2][1]+=a4.z*b4.y; acc[2][2]+=a4.z*b4.z; acc[2][3]+=a4.z*b4.w;
            acc[3][0]+=a4.w*b4.x; acc[3][1]+=a4.w*b4.y; acc[3][2]+=a4.w*b4.z; acc[3][3]+=a4.w*b4.w;
        }
        if (t+1 < T) {
            const int q = p ^ 1;
            As[q][ak][am]=ra.x; As[q][ak+1][am]=ra.y; As[q][ak+2][am]=ra.z; As[q][ak+3][am]=ra.w;
            *(float4*)&Bs[q][bk][bn] = rb0;
            *(float4*)&Bs[q][bk+8][bn] = rb1;
            __syncthreads();
        }
    }

    if (EPI == 0) {
        float4 bv = make_float4(0.f,0.f,0.f,0.f);
        if (bias) bv = *(const float4*)&bias[col0 + (tx<<2)];
        #pragma unroll
        for (int i = 0; i < 4; i++) {
            int gm = row0 + (ty<<2) + i;
            if (gm >= M) continue;
            float4 v = make_float4(acc[i][0]+bv.x, acc[i][1]+bv.y, acc[i][2]+bv.z, acc[i][3]+bv.w);
            *(float4*)&C[(size_t)gm*N + col0 + (tx<<2)] = v;
        }
    } else {
        const int h = (col0 >> 2) + tx;          // hidden unit index
        float4 bv = make_float4(0.f,0.f,0.f,0.f);
        if (bias) bv = *(const float4*)&bias[h<<2];
        #pragma unroll
        for (int i = 0; i < 4; i++) {
            int gm = row0 + (ty<<2) + i;
            if (gm >= M) continue;
            float gi = acc[i][0]+bv.x, gf = acc[i][1]+bv.y, gg = acc[i][2]+bv.z, go = acc[i][3]+bv.w;
            if (EPI == 1) {
                float cv = sigf(gi)*ftanh(gg);
                p1[gm*HID + h] = sigf(go)*ftanh(cv);
            } else if (EPI == 4) {
                float cp = p1[gm*512 + h];    // c0 prop
                float cv = sigf(gf)*cp + sigf(gi)*ftanh(gg);
                float hv = sigf(go)*ftanh(cv);
                p2[gm*H4 + h]       = cv;     // HC c0
                p2[gm*H4 + HID + h] = hv;     // HC h0
                p3[gm*512 + h]      = hv;     // XH2 first half
            } else {
                float cp = p1[gm*512 + HID + h];  // c1 prop
                float cv = sigf(gf)*cp + sigf(gi)*ftanh(gg);
                float hv = sigf(go)*ftanh(cv);
                p2[gm*H4 + 512 + h] = cv;     // HC c1
                p2[gm*H4 + 768 + h] = hv;     // HC h1
            }
        }
    }
}

// ---------------- skip-encoder step kernels (LN fused via partial-sum stats) --------
// Common prologue: rebuild mu/rsqrt for rows of this tile from fixed-order slot sums.
__device__ __forceinline__ void skip_stats(int row0, int actlim, int prv,
                                           float* smu, float* srs) {
    int tid = threadIdx.x;
    int rr = tid >> 2, q = tid & 3;
    int gm = row0 + rr;
    float s = 0.f, s2 = 0.f;
    if (gm < actlim) {
        #pragma unroll
        for (int e = 0; e < 8; e++) {
            int slot = q*8 + e;
            float2 v = (slot < 16) ? d_PSA[prv][gm][slot] : d_PSB[prv][gm][slot-16];
            s += v.x; s2 += v.y;
        }
    }
    s  += __shfl_xor_sync(0xffffffffu, s, 1);
    s  += __shfl_xor_sync(0xffffffffu, s, 2);
    s2 += __shfl_xor_sync(0xffffffffu, s2, 1);
    s2 += __shfl_xor_sync(0xffffffffu, s2, 2);
    if (q == 0) {
        float mu = s * (1.f/1024.f);
        float var = fmaxf(s2 * (1.f/1024.f) - mu*mu, 0.f);
        smu[rr] = mu;
        srs[rr] = rsqrtf(var + 1e-6f);
    }
}

// skip1: g0 = LN(h0_prev) @ Wh0 (+XG0) -> cell0 -> raw c0,h0 + partials
__global__ void __launch_bounds__(128) skip1_kernel(int idx,
        const float* __restrict__ lns, const float* __restrict__ lnb) {
    __shared__ float As[2][16][36];
    __shared__ float Bs[2][16][64];
    __shared__ float smu[32], srs[32];
    __shared__ float sls[256], slb[256];
    const int tid = threadIdx.x;
    const int tx = tid & 15, ty = tid >> 4;
    const int row0 = blockIdx.y << 5;
    const int col0 = blockIdx.x << 6;
    const int ct = blockIdx.x;
    const int cur = idx & 1, prv = cur ^ 1;
    const int actlim = idx << 3;
    const int M = (idx + 1) << 3;
    const float* rc0p = d_RC0 + prv*CHAINS*HID;
    const float* rh0p = d_RH0 + prv*CHAINS*HID;
    float* rc0c = d_RC0 + cur*CHAINS*HID;
    float* rh0c = d_RH0 + cur*CHAINS*HID;

    skip_stats(row0, actlim, prv, smu, srs);
    sls[tid]     = lns[256 + tid];
    sls[128+tid] = lns[384 + tid];
    slb[tid]     = lnb[256 + tid];
    slb[128+tid] = lnb[384 + tid];
    __syncthreads();

    const int am = tid >> 2;
    const int ak = (tid & 3) << 2;
    const int bk = tid >> 4;
    const int bn = (tid & 15) << 2;
    const int gA = row0 + am;
    const bool actA = gA < actlim;
    const float muA = smu[am], rsA = srs[am];
    const float* Arow = rh0p + (size_t)gA*HID;
    const float* Bg = d_SKH0f;
    float acc[4][4] = {};
    float4 ra, rb0, rb1;

    // prologue chunk 0
    {
        if (actA) {
            float4 v = *(const float4*)(Arow + ak);
            ra.x = (v.x-muA)*rsA*sls[ak]   + slb[ak];
            ra.y = (v.y-muA)*rsA*sls[ak+1] + slb[ak+1];
            ra.z = (v.z-muA)*rsA*sls[ak+2] + slb[ak+2];
            ra.w = (v.w-muA)*rsA*sls[ak+3] + slb[ak+3];
        } else ra = make_float4(0.f,0.f,0.f,0.f);
        rb0 = *(const float4*)&Bg[(size_t)bk*H4 + col0 + bn];
        rb1 = *(const float4*)&Bg[(size_t)(bk+8)*H4 + col0 + bn];
        As[0][ak&15][am]=ra.x; As[0][(ak&15)+1][am]=ra.y; As[0][(ak&15)+2][am]=ra.z; As[0][(ak&15)+3][am]=ra.w;
        *(float4*)&Bs[0][bk][bn] = rb0;
        *(float4*)&Bs[0][bk+8][bn] = rb1;
        __syncthreads();
    }
    for (int t = 0; t < 16; t++) {
        const int p = t & 1;
        if (t+1 < 16) {
            int k0 = (t+1) << 4;
            if (actA) {
                float4 v = *(const float4*)(Arow + k0 + ak);
                ra.x = (v.x-muA)*rsA*sls[k0+ak]   + slb[k0+ak];
                ra.y = (v.y-muA)*rsA*sls[k0+ak+1] + slb[k0+ak+1];
                ra.z = (v.z-muA)*rsA*sls[k0+ak+2] + slb[k0+ak+2];
                ra.w = (v.w-muA)*rsA*sls[k0+ak+3] + slb[k0+ak+3];
            } else ra = make_float4(0.f,0.f,0.f,0.f);
            rb0 = *(const float4*)&Bg[(size_t)(k0+bk)*H4 + col0 + bn];
            rb1 = *(const float4*)&Bg[(size_t)(k0+bk+8)*H4 + col0 + bn];
        }
        #pragma unroll
        for (int kk = 0; kk < 16; kk++) {
            float4 b4 = *(const float4*)&Bs[p][kk][tx<<2];
            float4 a4 = *(const float4*)&As[p][kk][ty<<2];
            acc[0][0]+=a4.x*b4.x; acc[0][1]+=a4.x*b4.y; acc[0][2]+=a4.x*b4.z; acc[0][3]+=a4.x*b4.w;
            acc[1][0]+=a4.y*b4.x; acc[1][1]+=a4.y*b4.y; acc[1][2]+=a4.y*b4.z; acc[1][3]+=a4.y*b4.w;
            acc[2][0]+=a4.z*b4.x; acc[2][1]+=a4.z*b4.y; acc[2][2]+=a4.z*b4.z; acc[2][3]+=a4.z*b4.w;
            acc[3][0]+=a4.w*b4.x; acc[3][1]+=a4.w*b4.y; acc[3][2]+=a4.w*b4.z; acc[3][3]+=a4.w*b4.w;
        }
        if (t+1 < 16) {
            const int q = p ^ 1;
            As[q][ak][am]=ra.x; As[q][ak+1][am]=ra.y; As[q][ak+2][am]=ra.z; As[q][ak+3][am]=ra.w;
            *(float4*)&Bs[q][bk][bn] = rb0;
            *(float4*)&Bs[q][bk+8][bn] = rb1;
            __syncthreads();
        }
    }

    // epilogue: cell0 + partial sums
    const int u = (col0 >> 2) + tx;
    #pragma unroll
    for (int i = 0; i < 4; i++) {
        int r = (ty<<2) + i;
        int gm = row0 + r;
        float pv = 0.f, p2v = 0.f;
        if (gm < M) {
            const float4 xv = *(const float4*)&d_XG0[((size_t)(gm & 7)*NSTMT + idx)*H4 + (u<<2)];
            float gi = acc[i][0]+xv.x, gf = acc[i][1]+xv.y;
            float gg = acc[i][2]+xv.z, go = acc[i][3]+xv.w;
            float c0p = (gm < actlim)
                ? (rc0p[(size_t)gm*HID + u] - smu[r])*srs[r]*lns[u] + lnb[u] : 0.f;
            float cv = sigf(gf)*c0p + sigf(gi)*ftanh(gg);
            float hv = sigf(go)*ftanh(cv);
            rc0c[(size_t)gm*HID + u] = cv;
            rh0c[(size_t)gm*HID + u] = hv;
            pv = cv + hv;
            p2v = cv*cv + hv*hv;
        }
        #pragma unroll
        for (int o = 1; o < 16; o <<= 1) {
            pv  += __shfl_xor_sync(0xffffffffu, pv, o);
            p2v += __shfl_xor_sync(0xffffffffu, p2v, o);
        }
        if (tx == 0 && gm < M) d_PSA[cur][gm][ct] = make_float2(pv, p2v);
    }
}

// skip2: g1 = h0_new @ Wx1 + LN(h1_prev) @ Wh1 + b -> cell1 -> raw c1,h1 + SKIP + partials
__global__ void __launch_bounds__(128) skip2_kernel(int idx,
        const float* __restrict__ lns, const float* __restrict__ lnb) {
    __shared__ float As[2][16][36];
    __shared__ float Bs[2][16][64];
    __shared__ float smu[32], srs[32];
    __shared__ float sls[256], slb[256];
    const int tid = threadIdx.x;
    const int tx = tid & 15, ty = tid >> 4;
    const int row0 = blockIdx.y << 5;
    const int col0 = blockIdx.x << 6;
    const int ct = blockIdx.x;
    const int cur = idx & 1, prv = cur ^ 1;
    const int actlim = idx << 3;
    const int M = (idx + 1) << 3;
    const float* rc1p = d_RC1 + prv*CHAINS*HID;
    const float* rh1p = d_RH1 + prv*CHAINS*HID;
    const float* rh0c = d_RH0 + cur*CHAINS*HID;
    float* rc1c = d_RC1 + cur*CHAINS*HID;
    float* rh1c = d_RH1 + cur*CHAINS*HID;

    skip_stats(row0, actlim, prv, smu, srs);
    sls[tid]     = lns[768 + tid];
    sls[128+tid] = lns[896 + tid];
    slb[tid]     = lnb[768 + tid];
    slb[128+tid] = lnb[896 + tid];
    __syncthreads();

    const int am = tid >> 2;
    const int ak = (tid & 3) << 2;
    const int bk = tid >> 4;
    const int bn = (tid & 15) << 2;
    const int gA = row0 + am;
    const bool inM = gA < M;
    const bool actA = gA < actlim;
    const float muA = smu[am], rsA = srs[am];
    const float* Arow0 = rh0c + (size_t)gA*HID;   // pass 0: raw h0 (current)
    const float* Arow1 = rh1p + (size_t)gA*HID;   // pass 1: h1 prev (LN on the fly)
    const float* Bg = d_SK1f;
    float acc[4][4] = {};
    float4 ra, rb0, rb1;

    // prologue chunk 0 (h0 path)
    {
        ra = inM ? *(const float4*)(Arow0 + ak) : make_float4(0.f,0.f,0.f,0.f);
        rb0 = *(const float4*)&Bg[(size_t)bk*H4 + col0 + bn];
        rb1 = *(const float4*)&Bg[(size_t)(bk+8)*H4 + col0 + bn];
        As[0][ak][am]=ra.x; As[0][ak+1][am]=ra.y; As[0][ak+2][am]=ra.z; As[0][ak+3][am]=ra.w;
        *(float4*)&Bs[0][bk][bn] = rb0;
        *(float4*)&Bs[0][bk+8][bn] = rb1;
        __syncthreads();
    }
    for (int t = 0; t < 32; t++) {
        const int p = t & 1;
        if (t+1 < 32) {
            int k0 = (t+1) << 4;
            if (k0 < 256) {
                ra = inM ? *(const float4*)(Arow0 + k0 + ak) : make_float4(0.f,0.f,0.f,0.f);
            } else {
                int kh = k0 - 256 + ak;
                if (actA) {
                    float4 v = *(const float4*)(Arow1 + kh);
                    ra.x = (v.x-muA)*rsA*sls[kh]   + slb[kh];
                    ra.y = (v.y-muA)*rsA*sls[kh+1] + slb[kh+1];
                    ra.z = (v.z-muA)*rsA*sls[kh+2] + slb[kh+2];
                    ra.w = (v.w-muA)*rsA*sls[kh+3] + slb[kh+3];
                } else ra = make_float4(0.f,0.f,0.f,0.f);
            }
            rb0 = *(const float4*)&Bg[(size_t)(k0+bk)*H4 + col0 + bn];
            rb1 = *(const float4*)&Bg[(size_t)(k0+bk+8)*H4 + col0 + bn];
        }
        #pragma unroll
        for (int kk = 0; kk < 16; kk++) {
            float4 b4 = *(const float4*)&Bs[p][kk][tx<<2];
            float4 a4 = *(const float4*)&As[p][kk][ty<<2];
            acc[0][0]+=a4.x*b4.x; acc[0][1]+=a4.x*b4.y; acc[0][2]+=a4.x*b4.z; acc[0][3]+=a4.x*b4.w;
            acc[1][0]+=a4.y*b4.x; acc[1][1]+=a4.y*b4.y; acc[1][2]+=a4.y*b4.z; acc[1][3]+=a4.y*b4.w;
            acc[2][0]+=a4.z*b4.x; acc[2][1]+=a4.z*b4.y; acc[2][2]+=a4.z*b4.z; acc[2][3]+=a4.z*b4.w;
            acc[3][0]+=a4.w*b4.x; acc[3][1]+=a4.w*b4.y; acc[3][2]+=a4.w*b4.z; acc[3][3]+=a4.w*b4.w;
        }
        if (t+1 < 32) {
            const int q = p ^ 1;
            As[q][ak][am]=ra.x; As[q][ak+1][am]=ra.y; As[q][ak+2][am]=ra.z; As[q][ak+3][am]=ra.w;
            *(float4*)&Bs[q][bk][bn] = rb0;
            *(float4*)&Bs[q][bk+8][bn] = rb1;
            __syncthreads();
        }
    }

    // epilogue: cell1 + SKIP + partial sums
    const int u = (col0 >> 2) + tx;
    const float4 bv = *(const float4*)&d_BSK1[u<<2];
    #pragma unroll
    for (int i = 0; i < 4; i++) {
        int r = (ty<<2) + i;
        int gm = row0 + r;
        float pv = 0.f, p2v = 0.f;
        if (gm < M) {
            float gi = acc[i][0]+bv.x, gf = acc[i][1]+bv.y;
            float gg = acc[i][2]+bv.z, go = acc[i][3]+bv.w;
            float c1p = (gm < actlim)
                ? (rc1p[(size_t)gm*HID + u] - smu[r])*srs[r]*lns[512+u] + lnb[512+u] : 0.f;
            float cv = sigf(gf)*c1p + sigf(gi)*ftanh(gg);
            float hv = sigf(go)*ftanh(cv);
            rc1c[(size_t)gm*HID + u] = cv;
            rh1c[(size_t)gm*HID + u] = hv;
            int s = gm >> 3, b = gm & 7;
            d_SKIP[(((size_t)b*NNODE + s)*NNODE + (idx+1))*HID + u] = hv;
            pv = cv + hv;
            p2v = cv*cv + hv*hv;
        }
        #pragma unroll
        for (int o = 1; o < 16; o <<= 1) {
            pv  += __shfl_xor_sync(0xffffffffu, pv, o);
            p2v += __shfl_xor_sync(0xffffffffu, p2v, o);
        }
        if (tx == 0 && gm < M) d_PSB[cur][gm][ct] = make_float2(pv, p2v);
    }
}

// ---------------- tensor-core GEMM for the big keys GEMM (bf16 hi/lo, plain epi) ----
__global__ void __launch_bounds__(128) gemm_mma0(
    const float* __restrict__ A, const __nv_bfloat16* __restrict__ Bh_g,
    const float* __restrict__ bias, float* __restrict__ C,
    int M, int K, int N)
{
    const __nv_bfloat16* Bl_g = Bh_g + (size_t)K*N;
    __shared__ __align__(16) __nv_bfloat16 sAh[64*ASTR];
    __shared__ __align__(16) __nv_bfloat16 sAl[64*ASTR];
    __shared__ __align__(16) __nv_bfloat16 sBh[32*BSTR];
    __shared__ __align__(16) __nv_bfloat16 sBl[32*BSTR];

    const int tid  = threadIdx.x;
    const int lane = tid & 31;
    const int wid  = tid >> 5;
    const int wr   = wid >> 1;
    const int wc   = wid & 1;
    const int row0 = blockIdx.y << 6;
    const int col0 = blockIdx.x << 6;

    const int arow = tid >> 1;
    const int akq  = (tid & 1) << 4;
    const bool aval = (row0 + arow) < M;
    const float* Ag = A + (size_t)(row0 + arow)*K + akq;
    const int seg0 = tid << 1;

    float acc[2][4][4];
    #pragma unroll
    for (int a = 0; a < 2; a++)
        #pragma unroll
        for (int b = 0; b < 4; b++)
            #pragma unroll
            for (int cc = 0; cc < 4; cc++) acc[a][b][cc] = 0.f;

    const int NC = K >> 5;
    for (int cidx = 0; cidx < NC; cidx++) {
        const int k0 = cidx << 5;
        float av[16];
        #pragma unroll
        for (int j = 0; j < 4; j++) {
            float4 f = aval ? *(const float4*)(Ag + k0 + 4*j) : make_float4(0.f,0.f,0.f,0.f);
            av[4*j]=f.x; av[4*j+1]=f.y; av[4*j+2]=f.z; av[4*j+3]=f.w;
        }
        uint4 bvh[2], bvl[2];
        #pragma unroll
        for (int s = 0; s < 2; s++) {
            int seg = seg0 + s;
            int krow = seg >> 3, nc = (seg & 7) << 3;
            size_t off = (size_t)(k0 + krow)*N + col0 + nc;
            bvh[s] = *(const uint4*)(Bh_g + off);
            bvl[s] = *(const uint4*)(Bl_g + off);
        }
        __syncthreads();
        #pragma unroll
        for (int e = 0; e < 8; e++) {
            unsigned ul;
            unsigned uh = pack_hl(av[2*e], av[2*e+1], ul);
            *reinterpret_cast<unsigned*>(&sAh[arow*ASTR + akq + 2*e]) = uh;
            *reinterpret_cast<unsigned*>(&sAl[arow*ASTR + akq + 2*e]) = ul;
        }
        #pragma unroll
        for (int s = 0; s < 2; s++) {
            int seg = seg0 + s;
            int krow = seg >> 3, nc = (seg & 7) << 3;
            *reinterpret_cast<uint4*>(&sBh[krow*BSTR + nc]) = bvh[s];
            *reinterpret_cast<uint4*>(&sBl[krow*BSTR + nc]) = bvl[s];
        }
        __syncthreads();
        #pragma unroll
        for (int kk = 0; kk < 2; kk++) {
            unsigned ah[2][4], al[2][4], bh[2][4], bl[2][4];
            const int kc = (kk << 4) + ((lane >> 4) << 3);
            #pragma unroll
            for (int mi = 0; mi < 2; mi++) {
                int r = wr*32 + mi*16 + (lane & 15);
                ldsm_x4(ah[mi], &sAh[r*ASTR + kc]);
                ldsm_x4(al[mi], &sAl[r*ASTR + kc]);
            }
            const int kr = (kk << 4) + (lane & 15);
            #pragma unroll
            for (int g2 = 0; g2 < 2; g2++) {
                int nc = wc*32 + g2*16 + ((lane >> 4) << 3);
                ldsm_x4_t(bh[g2], &sBh[kr*BSTR + nc]);
                ldsm_x4_t(bl[g2], &sBl[kr*BSTR + nc]);
            }
            #pragma unroll
            for (int mi = 0; mi < 2; mi++)
                #pragma unroll
                for (int nf = 0; nf < 4; nf++) {
                    const unsigned* pbh = &bh[nf>>1][(nf&1)<<1];
                    const unsigned* pbl = &bl[nf>>1][(nf&1)<<1];
                    mma_bf16(acc[mi][nf], ah[mi], pbh);
                    mma_bf16(acc[mi][nf], al[mi], pbh);
                    mma_bf16(acc[mi][nf], ah[mi], pbl);
                }
        }
    }

    #pragma unroll
    for (int mi = 0; mi < 2; mi++) {
        int gm0 = row0 + wr*32 + mi*16 + (lane >> 2);
        #pragma unroll
        for (int nf = 0; nf < 4; nf++) {
            int colb = col0 + wc*32 + nf*8 + ((lane & 3) << 1);
            float b0 = bias ? bias[colb] : 0.f;
            float b1 = bias ? bias[colb+1] : 0.f;
            if (gm0 < M) {
                float2 o = make_float2(acc[mi][nf][0]+b0, acc[mi][nf][1]+b1);
                *(float2*)&C[(size_t)gm0*N + colb] = o;
            }
            if (gm0+8 < M) {
                float2 o = make_float2(acc[mi][nf][2]+b0, acc[mi][nf][3]+b1);
                *(float2*)&C[(size_t)(gm0+8)*N + colb] = o;
            }
        }
    }
}

// ---------------- main-loop kernels ----------------
__global__ void __launch_bounds__(256) attn_kernel(const float* __restrict__ w1,
                                                   const float* __restrict__ b1, int step) {
    int bn = blockIdx.x;               // b*81 + n
    int n = bn % NNODE;
    __shared__ float qsh[HID], w1sh[HID], lg[NNODE];
    int tid = threadIdx.x;
    qsh[tid]  = d_Q[bn*HID + tid];
    w1sh[tid] = w1[tid];
    __syncthreads();
    int w = tid >> 5, lane = tid & 31;
    float b1v = b1[0];
    for (int m = w; m < NNODE; m += 8) {
        const float* kr = d_KEYS + ((size_t)bn*NNODE + m)*HID;
        float acc = 0.f;
        #pragma unroll 4
        for (int h = lane; h < HID; h += 32)
            acc += ftanh(qsh[h] + kr[h]) * w1sh[h];
        #pragma unroll
        for (int o = 16; o; o >>= 1) acc += __shfl_xor_sync(0xffffffffu, acc, o);
        if (lane == 0) {
            bool allowed = (step == 0) ? (m == 1)
                        : ((step == NSTEP-1) ? (m == NNODE-1)
                                             : (m > n || m == NNODE-1));
            lg[m] = allowed ? (acc + b1v) : -1e9f;
        }
    }
    __syncthreads();
    if (w == 0) {
        float mx = -1e30f;
        for (int m = lane; m < NNODE; m += 32) mx = fmaxf(mx, lg[m]);
        #pragma unroll
        for (int o = 16; o; o >>= 1) mx = fmaxf(mx, __shfl_xor_sync(0xffffffffu, mx, o));
        float sum = 0.f;
        for (int m = lane; m < NNODE; m += 32) { float e = expf(lg[m]-mx); lg[m] = e; sum += e; }
        #pragma unroll
        for (int o = 16; o; o >>= 1) sum += __shfl_xor_sync(0xffffffffu, sum, o);
        float scale = d_P[bn] / sum;
        for (int m = lane; m < NNODE; m += 32) d_T[bn*NNODE + m] = lg[m]*scale;
    }
}

// props: transition propagation + new p (newp folded in)
__global__ void __launch_bounds__(256) props_kernel() {
    int bm = blockIdx.x;
    int b = bm / NNODE, m = bm % NNODE;
    __shared__ float tsh[NNODE];
    int tid = threadIdx.x;
    if (tid < NNODE) tsh[tid] = d_T[(b*NNODE+tid)*NNODE + m];
    __syncthreads();
    float s = 0.f;
    for (int n = 0; n < NNODE; n++) s += tsh[n];
    float inv = 1.f / (s + 1e-7f);
    float ax=0.f, a0=0.f, a1=0.f, a2=0.f, a3=0.f;
    for (int n = 0; n < NNODE; n++) {
        float tv = tsh[n];
        if (tv == 0.f) continue;
        const float* sr = d_SKIP + (((size_t)b*NNODE+n)*NNODE + m)*HID;
        const float* hr = d_HC + (size_t)(b*NNODE+n)*H4;
        ax += tv*sr[tid];
        a0 += tv*hr[tid];      a1 += tv*hr[256+tid];
        a2 += tv*hr[512+tid];  a3 += tv*hr[768+tid];
    }
    d_XHE[bm*512 + tid]       = ax*inv;  // x_in
    d_CPR[bm*512 + tid]       = a0*inv;  // c0 prop
    d_XHE[bm*512 + 256 + tid] = a1*inv;  // h0 prop
    d_CPR[bm*512 + 256 + tid] = a2*inv;  // c1 prop
    d_XH2[bm*512 + 256 + tid] = a3*inv;  // h1 prop
    if (tid == 0) d_P[bm] = s;
}

// ---------------- output projection ----------------
__global__ void __launch_bounds__(256) out_kernel(const int* __restrict__ exit_idx,
                                                  const float* __restrict__ wo,
                                                  const float* __restrict__ bo,
                                                  float* __restrict__ out) {
    __shared__ float hex[BATCH][HID];
    int tid = threadIdx.x;
    for (int i = tid; i < BATCH*HID; i += 256) {
        int b = i >> 8, h = i & 255;
        hex[b][h] = d_HC[(size_t)(b*NNODE + exit_idx[b])*H4 + 768 + h];
    }
    __syncthreads();
    int col = blockIdx.x*256 + tid;
    if (col >= VOCAB) return;
    float acc[BATCH];
    #pragma unroll
    for (int b = 0; b < BATCH; b++) acc[b] = 0.f;
    for (int h = 0; h < HID; h++) {
        float wv = wo[(size_t)h*VOCAB + col];
        #pragma unroll
        for (int b = 0; b < BATCH; b++) acc[b] += hex[b][h]*wv;
    }
    float bv = bo[col];
    #pragma unroll
    for (int b = 0; b < BATCH; b++) out[b*VOCAB + col] = acc[b] + bv;
}

// ---------------- host ----------------
static inline float* sym(const void* s) {
    void* p = nullptr;
    cudaGetSymbolAddress(&p, s);
    return (float*)p;
}
static inline __nv_bfloat16* symb(const void* s) {
    void* p = nullptr;
    cudaGetSymbolAddress(&p, s);
    return (__nv_bfloat16*)p;
}

template<int EPI>
static inline void launch_gemm(const float* A, const float* B, const float* bias, float* C,
                               int M, int K, int N,
                               float* p1 = 0, float* p2 = 0, float* p3 = 0) {
    dim3 g(N/64, (M+31)/32);
    gemm_epi<EPI><<<g, 128>>>(A, B, bias, C, M, K, N, p1, p2, p3);
}

extern "C" void kernel_launch(void* const* d_in, const int* in_sizes, int n_in,
                              void* d_out, int out_size) {
    const float* node_emb = (const float*)d_in[0];
    const int*   exit_idx = (const int*)  d_in[10];
    const float* st_Wx = (const float*)d_in[12];
    const float* st_b  = (const float*)d_in[14];
    const float* sk_Wx = (const float*)d_in[15];
    const float* sk_Wh = (const float*)d_in[16];
    const float* sk_b  = (const float*)d_in[17];
    const float* ln_s  = (const float*)d_in[18];
    const float* ln_b  = (const float*)d_in[19];
    const float* ex_Wx = (const float*)d_in[20];
    const float* ex_Wh = (const float*)d_in[21];
    const float* ex_b  = (const float*)d_in[22];
    const float* wk = (const float*)d_in[23];
    const float* bk = (const float*)d_in[24];
    const float* ws = (const float*)d_in[25];
    const float* bs = (const float*)d_in[26];
    const float* w1 = (const float*)d_in[27];
    const float* b1 = (const float*)d_in[28];
    const float* wo = (const float*)d_in[29];
    const float* bo = (const float*)d_in[30];
    float* out = (float*)d_out;

    float* pSTMT = sym(d_STMT);
    float* pTMPH = sym(d_TMPH);
    float* pXG0  = sym(d_XG0);
    float* pSKIP = sym(d_SKIP);
    float* pKEYS = sym(d_KEYS);
    float* pHC   = sym(d_HC);
    float* pQ    = sym(d_Q);
    float* pXHE  = sym(d_XHE);
    float* pXH2  = sym(d_XH2);
    float* pCPR  = sym(d_CPR);
    float* pST0f = sym(d_ST0f);
    float* pST1f = sym(d_ST1f);
    float* pSKX0f= sym(d_SKX0f);
    float* pEX0f = sym(d_EX0f);
    float* pEX1f = sym(d_EX1f);
    __nv_bfloat16* pWSw = symb(d_WSw);
    float* pBST0 = sym(d_BST0);
    float* pBST1 = sym(d_BST1);
    float* pBSK0 = sym(d_BSK0);
    float* pBEX0 = sym(d_BEX0);
    float* pBEX1 = sym(d_BEX1);

    const int MB = BATCH*NSTMT;  // 640

    init_kernel<<<512, 256>>>();
    build_w<<<(512*H4 + 255)/256, 256>>>(st_Wx, sk_Wx, sk_Wh, ex_Wx, ex_Wh, ws);
    build_b<<<(H4 + 255)/256, 256>>>(st_b, sk_b, ex_b);

    // statement embedder: single LSTM step from zero state (h=0 => no Wh term)
    launch_gemm<1>(node_emb, pST0f, pBST0, nullptr, MB, HID, H4, pTMPH);
    launch_gemm<1>(pTMPH,    pST1f, pBST1, nullptr, MB, HID, H4, pSTMT);

    // xg0 = stmt @ skWx0 + skb0 (interleaved), shared by all 81 starts
    launch_gemm<0>(pSTMT, pSKX0f, pBSK0, pXG0, MB, HID, H4);

    // skip encoder: 80 steps, 2 fused launches each (LN folded into stats prologues)
    for (int idx = 0; idx < NSTMT; idx++) {
        int M = BATCH*(idx+1);
        dim3 g(16, (M+31)/32);
        skip1_kernel<<<g, 128>>>(idx, ln_s, ln_b);
        skip2_kernel<<<g, 128>>>(idx, ln_s, ln_b);
    }

    // keys = skip @ ws + bs  (big parallel GEMM -> tensor cores, bf16 hi/lo split)
    {
        int M = BATCH*NNODE*NNODE;
        dim3 g(HID/64, (M+63)/64);
        gemm_mma0<<<g, 128>>>(pSKIP, pWSw, bs, pKEYS, M, HID, HID);
    }

    // main interpreter loop
    for (int step = 0; step < NSTEP; step++) {
        launch_gemm<0>(pHC, wk, bk, pQ, CHAINS, H4, HID);
        attn_kernel<<<CHAINS, 256>>>(w1, b1, step);
        props_kernel<<<CHAINS, 256>>>();
        launch_gemm<4>(pXHE, pEX0f, pBEX0, nullptr, CHAINS, 512, H4,
                       pCPR, pHC, pXH2);
        launch_gemm<5>(pXH2, pEX1f, pBEX1, nullptr, CHAINS, 512, H4,
                       pCPR, pHC, nullptr);
    }

    out_kernel<<<(VOCAB + 255)/256, 256>>>(exit_idx, wo, bo, out);
}

// round 6
// speedup vs baseline: 2.5093x; 1.1720x over previous
#include <cuda_runtime.h>
#include <cuda_bf16.h>
#include <math.h>

// Problem constants
#define BATCH 8
#define NSTMT 80
#define NNODE 81
#define HID   256
#define H4    1024
#define NSTEP 8
#define VOCAB 30000
#define CHAINS (NNODE*BATCH)   // 648
#define NBP 296                // persistent grid (2/SM via launch_bounds)

#define ASTR 40   // mma smem A row stride (bf16)
#define BSTR 72   // mma smem B row stride

// ---------------- device scratch (allocation-free) ----------------
static __device__ float d_SKIP[BATCH*NNODE*NNODE*HID];   // [b][start][pos][h]
static __device__ float d_KEYS[BATCH*NNODE*NNODE*HID];
static __device__ float d_STMT[BATCH*NSTMT*HID];
static __device__ float d_TMPH[BATCH*NSTMT*HID];
static __device__ float d_XG0 [BATCH*NSTMT*H4];          // stmt@skWx0 + skb0 (interleaved)
// ping-pong raw skip-LSTM state
static __device__ float d_RC0[2*CHAINS*HID];
static __device__ float d_RH0[2*CHAINS*HID];
static __device__ float d_RC1[2*CHAINS*HID];
static __device__ float d_RH1[2*CHAINS*HID];
// deterministic per-(row, col-tile) partial sums of raw concat state: (sum, sumsq)
static __device__ float2 d_PSA[2][CHAINS][16];   // from phase A (c0,h0)
static __device__ float2 d_PSB[2][CHAINS][16];   // from phase B (c1,h1)
static __device__ float d_HC [CHAINS*H4];   // exec state: c0,h0,c1,h1
static __device__ float d_Q  [CHAINS*HID];
static __device__ float d_T  [BATCH*NNODE*NNODE];
static __device__ float d_P  [CHAINS];
static __device__ float d_XHE[CHAINS*512];  // [x_in, h0prop]
static __device__ float d_XH2[CHAINS*512];  // [h0new, h1prop]
static __device__ float d_CPR[CHAINS*512];  // [c0prop, c1prop]
// fp32 interleaved weights (col' = 4h + gate) for launch-path GEMMs
static __device__ float d_ST0f [HID*H4];
static __device__ float d_ST1f [HID*H4];
static __device__ float d_SKX0f[HID*H4];
static __device__ float d_EX0f [512*H4];   // [exWx0; exWh0]
static __device__ float d_EX1f [512*H4];   // [exWx1; exWh1]
// bf16 hi/lo splits for tensor-core paths
static __device__ __nv_bfloat16 d_SKH0w[2*HID*H4];   // skip L0 recurrent
static __device__ __nv_bfloat16 d_SK1w [2*512*H4];   // skip L1 [Wx1;Wh1]
static __device__ __nv_bfloat16 d_WSw  [2*HID*HID];  // keys
static __device__ float d_BST0[H4], d_BST1[H4], d_BSK0[H4], d_BSK1[H4], d_BEX0[H4], d_BEX1[H4];
// grid barrier state
static __device__ unsigned g_cnt;
static __device__ unsigned g_gen;

// ---------------- helpers ----------------
__device__ __forceinline__ float sigf(float x){ return 1.f/(1.f+__expf(-x)); }
__device__ __forceinline__ float ftanh(float x){ return 1.f - 2.f/(__expf(2.f*x)+1.f); }

__device__ __forceinline__ void grid_barrier() {
    __syncthreads();
    if (threadIdx.x == 0) {
        unsigned gen = *(volatile unsigned*)&g_gen;
        __threadfence();
        if (atomicAdd(&g_cnt, 1u) == (unsigned)(gridDim.x - 1)) {
            atomicExch(&g_cnt, 0u);
            __threadfence();
            atomicExch(&g_gen, gen + 1u);
        } else {
            while (*(volatile unsigned*)&g_gen == gen) { __nanosleep(64); }
        }
        __threadfence();
    }
    __syncthreads();
}

__device__ __forceinline__ void store_hl(__nv_bfloat16* base, int total, int i, float v) {
    __nv_bfloat16 h = __float2bfloat16(v);
    base[i] = h;
    base[total + i] = __float2bfloat16(v - __bfloat162float(h));
}
__device__ __forceinline__ unsigned pack_hl(float x0, float x1, unsigned& lo_out) {
    __nv_bfloat16 h0 = __float2bfloat16(x0);
    __nv_bfloat16 h1 = __float2bfloat16(x1);
    __nv_bfloat16 l0 = __float2bfloat16(x0 - __bfloat162float(h0));
    __nv_bfloat16 l1 = __float2bfloat16(x1 - __bfloat162float(h1));
    unsigned uh = (unsigned)__bfloat16_as_ushort(h0) | ((unsigned)__bfloat16_as_ushort(h1) << 16);
    lo_out      = (unsigned)__bfloat16_as_ushort(l0) | ((unsigned)__bfloat16_as_ushort(l1) << 16);
    return uh;
}
__device__ __forceinline__ void ldsm_x4(unsigned* r, const __nv_bfloat16* p) {
    unsigned addr = (unsigned)__cvta_generic_to_shared(p);
    asm volatile("ldmatrix.sync.aligned.m8n8.x4.shared.b16 {%0,%1,%2,%3}, [%4];"
        : "=r"(r[0]), "=r"(r[1]), "=r"(r[2]), "=r"(r[3]) : "r"(addr));
}
__device__ __forceinline__ void ldsm_x4_t(unsigned* r, const __nv_bfloat16* p) {
    unsigned addr = (unsigned)__cvta_generic_to_shared(p);
    asm volatile("ldmatrix.sync.aligned.m8n8.x4.trans.shared.b16 {%0,%1,%2,%3}, [%4];"
        : "=r"(r[0]), "=r"(r[1]), "=r"(r[2]), "=r"(r[3]) : "r"(addr));
}
__device__ __forceinline__ void mma_bf16(float* c, const unsigned* a, const unsigned* b) {
    asm volatile("mma.sync.aligned.m16n8k16.row.col.f32.bf16.bf16.f32 "
        "{%0,%1,%2,%3}, {%4,%5,%6,%7}, {%8,%9}, {%0,%1,%2,%3};"
        : "+f"(c[0]), "+f"(c[1]), "+f"(c[2]), "+f"(c[3])
        : "r"(a[0]), "r"(a[1]), "r"(a[2]), "r"(a[3]), "r"(b[0]), "r"(b[1]));
}

// ---------------- init / weight prep ----------------
__global__ void init_kernel() {
    int stride = gridDim.x * blockDim.x;
    int gid = blockIdx.x * blockDim.x + threadIdx.x;
    for (int i = gid; i < BATCH*NNODE*NNODE*HID; i += stride) d_SKIP[i] = 0.f;
    for (int i = gid; i < CHAINS*H4; i += stride) d_HC[i] = 0.f;
    for (int i = gid; i < CHAINS; i += stride) d_P[i] = (i % NNODE == 0) ? 1.f : 0.f;
    if (gid == 0) { g_cnt = 0u; g_gen = 0u; }
}

__global__ void build_w(const float* __restrict__ stWx, const float* __restrict__ skWx,
                        const float* __restrict__ skWh, const float* __restrict__ exWx,
                        const float* __restrict__ exWh, const float* __restrict__ ws) {
    int i = blockIdx.x*256 + threadIdx.x;
    if (i >= 512*H4) return;
    int k = i >> 10, n = i & 1023;
    int h = n >> 2, g = n & 3;
    int sc = h + 256*g;                 // source (non-interleaved) column
    const int L1 = 256*H4;
    float v;
    v = (k < 256) ? skWx[L1 + k*H4 + sc] : skWh[L1 + (k-256)*H4 + sc];
    store_hl(d_SK1w, 512*H4, i, v);
    d_EX0f[i] = (k < 256) ? exWx[k*H4 + sc]      : exWh[(k-256)*H4 + sc];
    d_EX1f[i] = (k < 256) ? exWx[L1 + k*H4 + sc] : exWh[L1 + (k-256)*H4 + sc];
    if (k < 256) {
        int j = k*H4 + n;
        d_ST0f[j]  = stWx[k*H4 + sc];
        d_ST1f[j]  = stWx[L1 + k*H4 + sc];
        d_SKX0f[j] = skWx[k*H4 + sc];
        store_hl(d_SKH0w, HID*H4, j, skWh[k*H4 + sc]);
    }
    if (i < HID*HID) store_hl(d_WSw, HID*HID, i, ws[i]);
}

__global__ void build_b(const float* __restrict__ st_b, const float* __restrict__ sk_b,
                        const float* __restrict__ ex_b) {
    int i = blockIdx.x*256 + threadIdx.x;
    if (i >= H4) return;
    int h = i >> 2, g = i & 3;
    int sc = h + 256*g;
    d_BST0[i] = st_b[sc];       d_BST1[i] = st_b[H4 + sc];
    d_BSK0[i] = sk_b[sc];       d_BSK1[i] = sk_b[H4 + sc];
    d_BEX0[i] = ex_b[sc];       d_BEX1[i] = ex_b[H4 + sc];
}

// ---------------- fp32 SIMT GEMM + fused LSTM epilogues (launch path) ----------------
template<int EPI>
__global__ void __launch_bounds__(128) gemm_epi(
    const float* __restrict__ A, const float* __restrict__ B,
    const float* __restrict__ bias, float* __restrict__ C,
    int M, int K, int N,
    float* __restrict__ p1, float* __restrict__ p2, float* __restrict__ p3)
{
    __shared__ float As[2][16][36];
    __shared__ float Bs[2][16][64];
    const int tid = threadIdx.x;
    const int tx = tid & 15, ty = tid >> 4;
    const int row0 = blockIdx.y * 32;
    const int col0 = blockIdx.x * 64;
    const int T = K >> 4;
    const int am = tid >> 2;
    const int ak = (tid & 3) << 2;
    const int bk = tid >> 4;
    const int bn = (tid & 15) << 2;
    const int gmA = row0 + am;
    float acc[4][4] = {};
    float4 ra, rb0, rb1;
    ra = (gmA < M) ? *(const float4*)&A[(size_t)gmA*K + ak] : make_float4(0.f,0.f,0.f,0.f);
    rb0 = *(const float4*)&B[(size_t)bk*N + col0 + bn];
    rb1 = *(const float4*)&B[(size_t)(bk+8)*N + col0 + bn];
    As[0][ak][am]=ra.x; As[0][ak+1][am]=ra.y; As[0][ak+2][am]=ra.z; As[0][ak+3][am]=ra.w;
    *(float4*)&Bs[0][bk][bn] = rb0;
    *(float4*)&Bs[0][bk+8][bn] = rb1;
    __syncthreads();
    for (int t = 0; t < T; t++) {
        const int p = t & 1;
        if (t+1 < T) {
            int k0 = (t+1) << 4;
            ra = (gmA < M) ? *(const float4*)&A[(size_t)gmA*K + k0 + ak] : make_float4(0.f,0.f,0.f,0.f);
            rb0 = *(const float4*)&B[(size_t)(k0+bk)*N + col0 + bn];
            rb1 = *(const float4*)&B[(size_t)(k0+bk+8)*N + col0 + bn];
        }
        #pragma unroll
        for (int kk = 0; kk < 16; kk++) {
            float4 b4 = *(const float4*)&Bs[p][kk][tx<<2];
            float4 a4 = *(const float4*)&As[p][kk][ty<<2];
            acc[0][0]+=a4.x*b4.x; acc[0][1]+=a4.x*b4.y; acc[0][2]+=a4.x*b4.z; acc[0][3]+=a4.x*b4.w;
            acc[1][0]+=a4.y*b4.x; acc[1][1]+=a4.y*b4.y; acc[1][2]+=a4.y*b4.z; acc[1][3]+=a4.y*b4.w;
            acc[2][0]+=a4.z*b4.x; acc[2][1]+=a4.z*b4.y; acc[2][2]+=a4.z*b4.z; acc[2][3]+=a4.z*b4.w;
            acc[3][0]+=a4.w*b4.x; acc[3][1]+=a4.w*b4.y; acc[3][2]+=a4.w*b4.z; acc[3][3]+=a4.w*b4.w;
        }
        if (t+1 < T) {
            const int q = p ^ 1;
            As[q][ak][am]=ra.x; As[q][ak+1][am]=ra.y; As[q][ak+2][am]=ra.z; As[q][ak+3][am]=ra.w;
            *(float4*)&Bs[q][bk][bn] = rb0;
            *(float4*)&Bs[q][bk+8][bn] = rb1;
            __syncthreads();
        }
    }

    if (EPI == 0) {
        float4 bv = make_float4(0.f,0.f,0.f,0.f);
        if (bias) bv = *(const float4*)&bias[col0 + (tx<<2)];
        #pragma unroll
        for (int i = 0; i < 4; i++) {
            int gm = row0 + (ty<<2) + i;
            if (gm >= M) continue;
            float4 v = make_float4(acc[i][0]+bv.x, acc[i][1]+bv.y, acc[i][2]+bv.z, acc[i][3]+bv.w);
            *(float4*)&C[(size_t)gm*N + col0 + (tx<<2)] = v;
        }
    } else {
        const int h = (col0 >> 2) + tx;          // hidden unit index
        float4 bv = make_float4(0.f,0.f,0.f,0.f);
        if (bias) bv = *(const float4*)&bias[h<<2];
        #pragma unroll
        for (int i = 0; i < 4; i++) {
            int gm = row0 + (ty<<2) + i;
            if (gm >= M) continue;
            float gi = acc[i][0]+bv.x, gf = acc[i][1]+bv.y, gg = acc[i][2]+bv.z, go = acc[i][3]+bv.w;
            if (EPI == 1) {
                float cv = sigf(gi)*ftanh(gg);
                p1[gm*HID + h] = sigf(go)*ftanh(cv);
            } else if (EPI == 4) {
                float cp = p1[gm*512 + h];    // c0 prop
                float cv = sigf(gf)*cp + sigf(gi)*ftanh(gg);
                float hv = sigf(go)*ftanh(cv);
                p2[gm*H4 + h]       = cv;     // HC c0
                p2[gm*H4 + HID + h] = hv;     // HC h0
                p3[gm*512 + h]      = hv;     // XH2 first half
            } else {
                float cp = p1[gm*512 + HID + h];  // c1 prop
                float cv = sigf(gf)*cp + sigf(gi)*ftanh(gg);
                float hv = sigf(go)*ftanh(cv);
                p2[gm*H4 + 512 + h] = cv;     // HC c1
                p2[gm*H4 + 768 + h] = hv;     // HC h1
            }
        }
    }
}

// ---------------- persistent skip encoder: tensor-core tiles + fused LN ----------------
struct PSmem {
    __nv_bfloat16 Ah[2][32*ASTR];
    __nv_bfloat16 Al[2][32*ASTR];
    __nv_bfloat16 Bh[2][32*BSTR];
    __nv_bfloat16 Bl[2][32*BSTR];
    float lns[1024], lnb[1024];
    float mu[32], rs[32];
    float2 ps[32][2];
};

template<int PHASE>
__device__ __forceinline__ void skip_tile(
    PSmem& sm, int t, int idx, int actlim, int M, int prv, int cur,
    const float* __restrict__ rh_prev,   // LN'd-on-the-fly A source (h0p / h1p)
    const float* __restrict__ rc_prev,   // carry prev (c0p / c1p)
    const float* __restrict__ rh0_cur,   // phase B pass-0 A source
    float* __restrict__ rc_out, float* __restrict__ rh_out,
    const __nv_bfloat16* __restrict__ WBh, const __nv_bfloat16* __restrict__ WBl)
{
    const int tid = threadIdx.x;
    const int lane = tid & 31, wid = tid >> 5;
    const int wr = wid >> 1, wc = wid & 1;
    const int rt = t >> 4, ct = t & 15;
    const int row0 = rt << 5, col0 = ct << 6;

    // ---- LN stats from prev-step partial sums ----
    {
        int rr = tid >> 2, q = tid & 3;
        int gm = row0 + rr;
        float s = 0.f, s2 = 0.f;
        if (gm < actlim) {
            #pragma unroll
            for (int e = 0; e < 8; e++) {
                int slot = q*8 + e;
                float2 v = (slot < 16) ? __ldcg(&d_PSA[prv][gm][slot])
                                       : __ldcg(&d_PSB[prv][gm][slot-16]);
                s += v.x; s2 += v.y;
            }
        }
        s  += __shfl_xor_sync(0xffffffffu, s, 1);
        s  += __shfl_xor_sync(0xffffffffu, s, 2);
        s2 += __shfl_xor_sync(0xffffffffu, s2, 1);
        s2 += __shfl_xor_sync(0xffffffffu, s2, 2);
        if (q == 0) {
            float mu = s * (1.f/1024.f);
            float var = fmaxf(s2 * (1.f/1024.f) - mu*mu, 0.f);
            sm.mu[rr] = mu;
            sm.rs[rr] = rsqrtf(var + 1e-6f);
        }
    }
    __syncthreads();

    // ---- prefetch raw carry for epilogue ----
    float cpr[2][4];
    const int gm0 = row0 + wr*16 + (lane >> 2);
    #pragma unroll
    for (int rr = 0; rr < 2; rr++)
        #pragma unroll
        for (int nf = 0; nf < 4; nf++) {
            int colb = col0 + wc*32 + nf*8 + ((lane & 3) << 1);
            int u = colb >> 2;
            int gm = gm0 + rr*8;
            cpr[rr][nf] = (gm < actlim) ? __ldcg(rc_prev + (size_t)gm*HID + u) : 0.f;
        }

    // ---- pipelined GEMM over k chunks of 32 ----
    const int NC = (PHASE == 0) ? 8 : 16;
    const int arow = tid >> 2, acol = (tid & 3) << 3;
    const int brow = tid >> 2, bcol = (tid & 3) << 4;
    const int gA = row0 + arow;
    const float muA = sm.mu[arow], rsA = sm.rs[arow];
    float acc[4][4];
    #pragma unroll
    for (int a = 0; a < 4; a++)
        #pragma unroll
        for (int b = 0; b < 4; b++) acc[a][b] = 0.f;

    float4 ra0, ra1;
    uint4 wh0, wh1, wl0, wl1;
    bool actA = false, lnA = false;
    int kbA = 0;

    // loadA(c): raw fp32 A chunk + flags
    #define LOAD_A(c) do {                                                        \
        int k0_ = (c) << 5;                                                       \
        const float* src_; bool act_; bool ln_; int kk0_;                         \
        if (PHASE == 0) { src_ = rh_prev; act_ = (gA < actlim); ln_ = true; kk0_ = k0_; } \
        else if (k0_ < 256) { src_ = rh0_cur; act_ = (gA < M); ln_ = false; kk0_ = k0_; } \
        else { src_ = rh_prev; act_ = (gA < actlim); ln_ = true; kk0_ = k0_ - 256; } \
        actA = act_; lnA = ln_; kbA = kk0_ + acol;                                \
        if (act_) {                                                               \
            ra0 = __ldcg((const float4*)(src_ + (size_t)gA*HID + kk0_ + acol));   \
            ra1 = __ldcg((const float4*)(src_ + (size_t)gA*HID + kk0_ + acol + 4)); \
        } else { ra0 = make_float4(0.f,0.f,0.f,0.f); ra1 = ra0; }                 \
    } while(0)

    #define LOAD_B(c) do {                                                        \
        int k0_ = (c) << 5;                                                       \
        size_t off_ = (size_t)(k0_ + brow)*H4 + col0 + bcol;                      \
        wh0 = *(const uint4*)(WBh + off_); wh1 = *(const uint4*)(WBh + off_ + 8); \
        wl0 = *(const uint4*)(WBl + off_); wl1 = *(const uint4*)(WBl + off_ + 8); \
    } while(0)

    #define STORE_AB(buf) do {                                                    \
        float v_[8] = {ra0.x, ra0.y, ra0.z, ra0.w, ra1.x, ra1.y, ra1.z, ra1.w};   \
        if (actA && lnA) {                                                        \
            const int lo_ = (PHASE == 0) ? 256 : 768;                             \
            _Pragma("unroll")                                                     \
            for (int e_ = 0; e_ < 8; e_++)                                        \
                v_[e_] = (v_[e_] - muA)*rsA*sm.lns[lo_ + kbA + e_] + sm.lnb[lo_ + kbA + e_]; \
        }                                                                         \
        _Pragma("unroll")                                                         \
        for (int e_ = 0; e_ < 4; e_++) {                                          \
            unsigned ul_;                                                         \
            unsigned uh_ = pack_hl(v_[2*e_], v_[2*e_+1], ul_);                    \
            *reinterpret_cast<unsigned*>(&sm.Ah[buf][arow*ASTR + acol + 2*e_]) = uh_; \
            *reinterpret_cast<unsigned*>(&sm.Al[buf][arow*ASTR + acol + 2*e_]) = ul_; \
        }                                                                         \
        *(uint4*)&sm.Bh[buf][brow*BSTR + bcol] = wh0;                             \
        *(uint4*)&sm.Bh[buf][brow*BSTR + bcol + 8] = wh1;                         \
        *(uint4*)&sm.Bl[buf][brow*BSTR + bcol] = wl0;                             \
        *(uint4*)&sm.Bl[buf][brow*BSTR + bcol + 8] = wl1;                         \
    } while(0)

    LOAD_A(0); LOAD_B(0);
    STORE_AB(0);
    __syncthreads();
    for (int c = 0; c < NC; c++) {
        const int p = c & 1;
        if (c + 1 < NC) { LOAD_A(c+1); LOAD_B(c+1); }
        // compute from buffer p
        #pragma unroll
        for (int kk = 0; kk < 2; kk++) {
            unsigned ah[4], al[4], bh[2][4], bl[2][4];
            const int kc = (kk << 4) + ((lane >> 4) << 3);
            const int r = wr*16 + (lane & 15);
            ldsm_x4(ah, &sm.Ah[p][r*ASTR + kc]);
            ldsm_x4(al, &sm.Al[p][r*ASTR + kc]);
            const int kr = (kk << 4) + (lane & 15);
            #pragma unroll
            for (int g2 = 0; g2 < 2; g2++) {
                int nc = wc*32 + g2*16 + ((lane >> 4) << 3);
                ldsm_x4_t(bh[g2], &sm.Bh[p][kr*BSTR + nc]);
                ldsm_x4_t(bl[g2], &sm.Bl[p][kr*BSTR + nc]);
            }
            #pragma unroll
            for (int nf = 0; nf < 4; nf++) {
                const unsigned* pbh = &bh[nf>>1][(nf&1)<<1];
                const unsigned* pbl = &bl[nf>>1][(nf&1)<<1];
                mma_bf16(acc[nf], ah, pbh);
                mma_bf16(acc[nf], al, pbh);
                mma_bf16(acc[nf], ah, pbl);
            }
        }
        if (c + 1 < NC) {
            STORE_AB(p ^ 1);
            __syncthreads();
        }
    }
    #undef LOAD_A
    #undef LOAD_B
    #undef STORE_AB

    // ---- epilogue: LSTM cell + raw state + partial sums ----
    float pv[2] = {0.f, 0.f}, p2v[2] = {0.f, 0.f};
    #pragma unroll
    for (int nf = 0; nf < 4; nf++) {
        float v0 = acc[nf][0], v1 = acc[nf][1], v2 = acc[nf][2], v3 = acc[nf][3];
        float s0 = __shfl_xor_sync(0xffffffffu, v0, 1);
        float s1 = __shfl_xor_sync(0xffffffffu, v1, 1);
        float s2 = __shfl_xor_sync(0xffffffffu, v2, 1);
        float s3 = __shfl_xor_sync(0xffffffffu, v3, 1);
        if (!(lane & 1)) {
            int colb = col0 + wc*32 + nf*8 + ((lane & 3) << 1);
            int u = colb >> 2;
            #pragma unroll
            for (int rr = 0; rr < 2; rr++) {
                int gm = gm0 + rr*8;
                if (gm < M) {
                    int r = gm - row0;
                    float gi = (rr ? v2 : v0), gf = (rr ? v3 : v1);
                    float gg = (rr ? s2 : s0), go = (rr ? s3 : s1);
                    float cp;
                    if (PHASE == 0) {
                        float4 xv = *(const float4*)&d_XG0[((size_t)(gm & 7)*NSTMT + idx)*H4 + (u<<2)];
                        gi += xv.x; gf += xv.y; gg += xv.z; go += xv.w;
                        cp = (gm < actlim)
                           ? (cpr[rr][nf] - sm.mu[r])*sm.rs[r]*sm.lns[u] + sm.lnb[u] : 0.f;
                    } else {
                        float4 bv = *(const float4*)&d_BSK1[u<<2];
                        gi += bv.x; gf += bv.y; gg += bv.z; go += bv.w;
                        cp = (gm < actlim)
                           ? (cpr[rr][nf] - sm.mu[r])*sm.rs[r]*sm.lns[512+u] + sm.lnb[512+u] : 0.f;
                    }
                    float cv = sigf(gf)*cp + sigf(gi)*ftanh(gg);
                    float hv = sigf(go)*ftanh(cv);
                    rc_out[(size_t)gm*HID + u] = cv;
                    rh_out[(size_t)gm*HID + u] = hv;
                    if (PHASE == 1) {
                        int s = gm >> 3, b = gm & 7;
                        d_SKIP[(((size_t)b*NNODE + s)*NNODE + (idx+1))*HID + u] = hv;
                    }
                    pv[rr]  += cv + hv;
                    p2v[rr] += cv*cv + hv*hv;
                }
            }
        }
    }
    #pragma unroll
    for (int rr = 0; rr < 2; rr++) {
        pv[rr]  += __shfl_xor_sync(0xffffffffu, pv[rr], 2);
        p2v[rr] += __shfl_xor_sync(0xffffffffu, p2v[rr], 2);
        if ((lane & 3) == 0) {
            int rit = wr*16 + (lane >> 2) + rr*8;
            sm.ps[rit][wc] = make_float2(pv[rr], p2v[rr]);
        }
    }
    __syncthreads();
    if (tid < 32) {
        int gm = row0 + tid;
        if (gm < M) {
            float2 a = sm.ps[tid][0], b = sm.ps[tid][1];
            float2 o = make_float2(a.x + b.x, a.y + b.y);
            if (PHASE == 0) d_PSA[cur][gm][ct] = o;
            else            d_PSB[cur][gm][ct] = o;
        }
    }
    __syncthreads();
}

__global__ void __launch_bounds__(128, 2) skip_persist(
    const float* __restrict__ lns, const float* __restrict__ lnb)
{
    __shared__ __align__(16) PSmem sm;
    const int tid = threadIdx.x;
    for (int i = tid; i < 1024; i += 128) { sm.lns[i] = lns[i]; sm.lnb[i] = lnb[i]; }
    __syncthreads();

    for (int idx = 0; idx < NSTMT; idx++) {
        const int M = (idx + 1) << 3;
        const int actlim = idx << 3;
        const int cur = idx & 1, prv = cur ^ 1;
        const int RT = (M + 31) >> 5;
        const int NT = RT << 4;
        const float* rh0p = d_RH0 + prv*CHAINS*HID;
        const float* rc0p = d_RC0 + prv*CHAINS*HID;
        const float* rh1p = d_RH1 + prv*CHAINS*HID;
        const float* rc1p = d_RC1 + prv*CHAINS*HID;
        float* rh0c = d_RH0 + cur*CHAINS*HID;
        float* rc0c = d_RC0 + cur*CHAINS*HID;
        float* rh1c = d_RH1 + cur*CHAINS*HID;
        float* rc1c = d_RC1 + cur*CHAINS*HID;

        for (int t = blockIdx.x; t < NT; t += NBP)
            skip_tile<0>(sm, t, idx, actlim, M, prv, cur,
                         rh0p, rc0p, nullptr, rc0c, rh0c,
                         d_SKH0w, d_SKH0w + HID*H4);
        grid_barrier();
        for (int t = blockIdx.x; t < NT; t += NBP)
            skip_tile<1>(sm, t, idx, actlim, M, prv, cur,
                         rh1p, rc1p, rh0c, rc1c, rh1c,
                         d_SK1w, d_SK1w + 512*H4);
        grid_barrier();
    }
}

// ---------------- tensor-core GEMM for the big keys GEMM (bf16 hi/lo, plain epi) ----
__global__ void __launch_bounds__(128) gemm_mma0(
    const float* __restrict__ A, const __nv_bfloat16* __restrict__ Bh_g,
    const float* __restrict__ bias, float* __restrict__ C,
    int M, int K, int N)
{
    const __nv_bfloat16* Bl_g = Bh_g + (size_t)K*N;
    __shared__ __align__(16) __nv_bfloat16 sAh[64*ASTR];
    __shared__ __align__(16) __nv_bfloat16 sAl[64*ASTR];
    __shared__ __align__(16) __nv_bfloat16 sBh[32*BSTR];
    __shared__ __align__(16) __nv_bfloat16 sBl[32*BSTR];

    const int tid  = threadIdx.x;
    const int lane = tid & 31;
    const int wid  = tid >> 5;
    const int wr   = wid >> 1;
    const int wc   = wid & 1;
    const int row0 = blockIdx.y << 6;
    const int col0 = blockIdx.x << 6;

    const int arow = tid >> 1;
    const int akq  = (tid & 1) << 4;
    const bool aval = (row0 + arow) < M;
    const float* Ag = A + (size_t)(row0 + arow)*K + akq;
    const int seg0 = tid << 1;

    float acc[2][4][4];
    #pragma unroll
    for (int a = 0; a < 2; a++)
        #pragma unroll
        for (int b = 0; b < 4; b++)
            #pragma unroll
            for (int cc = 0; cc < 4; cc++) acc[a][b][cc] = 0.f;

    const int NC = K >> 5;
    for (int cidx = 0; cidx < NC; cidx++) {
        const int k0 = cidx << 5;
        float av[16];
        #pragma unroll
        for (int j = 0; j < 4; j++) {
            float4 f = aval ? *(const float4*)(Ag + k0 + 4*j) : make_float4(0.f,0.f,0.f,0.f);
            av[4*j]=f.x; av[4*j+1]=f.y; av[4*j+2]=f.z; av[4*j+3]=f.w;
        }
        uint4 bvh[2], bvl[2];
        #pragma unroll
        for (int s = 0; s < 2; s++) {
            int seg = seg0 + s;
            int krow = seg >> 3, nc = (seg & 7) << 3;
            size_t off = (size_t)(k0 + krow)*N + col0 + nc;
            bvh[s] = *(const uint4*)(Bh_g + off);
            bvl[s] = *(const uint4*)(Bl_g + off);
        }
        __syncthreads();
        #pragma unroll
        for (int e = 0; e < 8; e++) {
            unsigned ul;
            unsigned uh = pack_hl(av[2*e], av[2*e+1], ul);
            *reinterpret_cast<unsigned*>(&sAh[arow*ASTR + akq + 2*e]) = uh;
            *reinterpret_cast<unsigned*>(&sAl[arow*ASTR + akq + 2*e]) = ul;
        }
        #pragma unroll
        for (int s = 0; s < 2; s++) {
            int seg = seg0 + s;
            int krow = seg >> 3, nc = (seg & 7) << 3;
            *reinterpret_cast<uint4*>(&sBh[krow*BSTR + nc]) = bvh[s];
            *reinterpret_cast<uint4*>(&sBl[krow*BSTR + nc]) = bvl[s];
        }
        __syncthreads();
        #pragma unroll
        for (int kk = 0; kk < 2; kk++) {
            unsigned ah[2][4], al[2][4], bh[2][4], bl[2][4];
            const int kc = (kk << 4) + ((lane >> 4) << 3);
            #pragma unroll
            for (int mi = 0; mi < 2; mi++) {
                int r = wr*32 + mi*16 + (lane & 15);
                ldsm_x4(ah[mi], &sAh[r*ASTR + kc]);
                ldsm_x4(al[mi], &sAl[r*ASTR + kc]);
            }
            const int kr = (kk << 4) + (lane & 15);
            #pragma unroll
            for (int g2 = 0; g2 < 2; g2++) {
                int nc = wc*32 + g2*16 + ((lane >> 4) << 3);
                ldsm_x4_t(bh[g2], &sBh[kr*BSTR + nc]);
                ldsm_x4_t(bl[g2], &sBl[kr*BSTR + nc]);
            }
            #pragma unroll
            for (int mi = 0; mi < 2; mi++)
                #pragma unroll
                for (int nf = 0; nf < 4; nf++) {
                    const unsigned* pbh = &bh[nf>>1][(nf&1)<<1];
                    const unsigned* pbl = &bl[nf>>1][(nf&1)<<1];
                    mma_bf16(acc[mi][nf], ah[mi], pbh);
                    mma_bf16(acc[mi][nf], al[mi], pbh);
                    mma_bf16(acc[mi][nf], ah[mi], pbl);
                }
        }
    }

    #pragma unroll
    for (int mi = 0; mi < 2; mi++) {
        int gm0 = row0 + wr*32 + mi*16 + (lane >> 2);
        #pragma unroll
        for (int nf = 0; nf < 4; nf++) {
            int colb = col0 + wc*32 + nf*8 + ((lane & 3) << 1);
            float b0 = bias ? bias[colb] : 0.f;
            float b1 = bias ? bias[colb+1] : 0.f;
            if (gm0 < M) {
                float2 o = make_float2(acc[mi][nf][0]+b0, acc[mi][nf][1]+b1);
                *(float2*)&C[(size_t)gm0*N + colb] = o;
            }
            if (gm0+8 < M) {
                float2 o = make_float2(acc[mi][nf][2]+b0, acc[mi][nf][3]+b1);
                *(float2*)&C[(size_t)(gm0+8)*N + colb] = o;
            }
        }
    }
}

// ---------------- main-loop kernels ----------------
__global__ void __launch_bounds__(256) attn_kernel(const float* __restrict__ w1,
                                                   const float* __restrict__ b1, int step) {
    int bn = blockIdx.x;               // b*81 + n
    int n = bn % NNODE;
    __shared__ float qsh[HID], w1sh[HID], lg[NNODE];
    int tid = threadIdx.x;
    qsh[tid]  = d_Q[bn*HID + tid];
    w1sh[tid] = w1[tid];
    __syncthreads();
    int w = tid >> 5, lane = tid & 31;
    float b1v = b1[0];
    for (int m = w; m < NNODE; m += 8) {
        const float* kr = d_KEYS + ((size_t)bn*NNODE + m)*HID;
        float acc = 0.f;
        #pragma unroll 4
        for (int h = lane; h < HID; h += 32)
            acc += ftanh(qsh[h] + kr[h]) * w1sh[h];
        #pragma unroll
        for (int o = 16; o; o >>= 1) acc += __shfl_xor_sync(0xffffffffu, acc, o);
        if (lane == 0) {
            bool allowed = (step == 0) ? (m == 1)
                        : ((step == NSTEP-1) ? (m == NNODE-1)
                                             : (m > n || m == NNODE-1));
            lg[m] = allowed ? (acc + b1v) : -1e9f;
        }
    }
    __syncthreads();
    if (w == 0) {
        float mx = -1e30f;
        for (int m = lane; m < NNODE; m += 32) mx = fmaxf(mx, lg[m]);
        #pragma unroll
        for (int o = 16; o; o >>= 1) mx = fmaxf(mx, __shfl_xor_sync(0xffffffffu, mx, o));
        float sum = 0.f;
        for (int m = lane; m < NNODE; m += 32) { float e = expf(lg[m]-mx); lg[m] = e; sum += e; }
        #pragma unroll
        for (int o = 16; o; o >>= 1) sum += __shfl_xor_sync(0xffffffffu, sum, o);
        float scale = d_P[bn] / sum;
        for (int m = lane; m < NNODE; m += 32) d_T[bn*NNODE + m] = lg[m]*scale;
    }
}

__global__ void __launch_bounds__(256) props_kernel() {
    int bm = blockIdx.x;
    int b = bm / NNODE, m = bm % NNODE;
    __shared__ float tsh[NNODE];
    int tid = threadIdx.x;
    if (tid < NNODE) tsh[tid] = d_T[(b*NNODE+tid)*NNODE + m];
    __syncthreads();
    float s = 0.f;
    for (int n = 0; n < NNODE; n++) s += tsh[n];
    float inv = 1.f / (s + 1e-7f);
    float ax=0.f, a0=0.f, a1=0.f, a2=0.f, a3=0.f;
    for (int n = 0; n < NNODE; n++) {
        float tv = tsh[n];
        if (tv == 0.f) continue;
        const float* sr = d_SKIP + (((size_t)b*NNODE+n)*NNODE + m)*HID;
        const float* hr = d_HC + (size_t)(b*NNODE+n)*H4;
        ax += tv*sr[tid];
        a0 += tv*hr[tid];      a1 += tv*hr[256+tid];
        a2 += tv*hr[512+tid];  a3 += tv*hr[768+tid];
    }
    d_XHE[bm*512 + tid]       = ax*inv;  // x_in
    d_CPR[bm*512 + tid]       = a0*inv;  // c0 prop
    d_XHE[bm*512 + 256 + tid] = a1*inv;  // h0 prop
    d_CPR[bm*512 + 256 + tid] = a2*inv;  // c1 prop
    d_XH2[bm*512 + 256 + tid] = a3*inv;  // h1 prop
    if (tid == 0) d_P[bm] = s;
}

// ---------------- output projection ----------------
__global__ void __launch_bounds__(256) out_kernel(const int* __restrict__ exit_idx,
                                                  const float* __restrict__ wo,
                                                  const float* __restrict__ bo,
                                                  float* __restrict__ out) {
    __shared__ float hex[BATCH][HID];
    int tid = threadIdx.x;
    for (int i = tid; i < BATCH*HID; i += 256) {
        int b = i >> 8, h = i & 255;
        hex[b][h] = d_HC[(size_t)(b*NNODE + exit_idx[b])*H4 + 768 + h];
    }
    __syncthreads();
    int col = blockIdx.x*256 + tid;
    if (col >= VOCAB) return;
    float acc[BATCH];
    #pragma unroll
    for (int b = 0; b < BATCH; b++) acc[b] = 0.f;
    for (int h = 0; h < HID; h++) {
        float wv = wo[(size_t)h*VOCAB + col];
        #pragma unroll
        for (int b = 0; b < BATCH; b++) acc[b] += hex[b][h]*wv;
    }
    float bv = bo[col];
    #pragma unroll
    for (int b = 0; b < BATCH; b++) out[b*VOCAB + col] = acc[b] + bv;
}

// ---------------- host ----------------
static inline float* sym(const void* s) {
    void* p = nullptr;
    cudaGetSymbolAddress(&p, s);
    return (float*)p;
}
static inline __nv_bfloat16* symb(const void* s) {
    void* p = nullptr;
    cudaGetSymbolAddress(&p, s);
    return (__nv_bfloat16*)p;
}

template<int EPI>
static inline void launch_gemm(const float* A, const float* B, const float* bias, float* C,
                               int M, int K, int N,
                               float* p1 = 0, float* p2 = 0, float* p3 = 0) {
    dim3 g(N/64, (M+31)/32);
    gemm_epi<EPI><<<g, 128>>>(A, B, bias, C, M, K, N, p1, p2, p3);
}

extern "C" void kernel_launch(void* const* d_in, const int* in_sizes, int n_in,
                              void* d_out, int out_size) {
    const float* node_emb = (const float*)d_in[0];
    const int*   exit_idx = (const int*)  d_in[10];
    const float* st_Wx = (const float*)d_in[12];
    const float* st_b  = (const float*)d_in[14];
    const float* sk_Wx = (const float*)d_in[15];
    const float* sk_Wh = (const float*)d_in[16];
    const float* sk_b  = (const float*)d_in[17];
    const float* ln_s  = (const float*)d_in[18];
    const float* ln_b  = (const float*)d_in[19];
    const float* ex_Wx = (const float*)d_in[20];
    const float* ex_Wh = (const float*)d_in[21];
    const float* ex_b  = (const float*)d_in[22];
    const float* wk = (const float*)d_in[23];
    const float* bk = (const float*)d_in[24];
    const float* ws = (const float*)d_in[25];
    const float* bs = (const float*)d_in[26];
    const float* w1 = (const float*)d_in[27];
    const float* b1 = (const float*)d_in[28];
    const float* wo = (const float*)d_in[29];
    const float* bo = (const float*)d_in[30];
    float* out = (float*)d_out;

    float* pSTMT = sym(d_STMT);
    float* pTMPH = sym(d_TMPH);
    float* pXG0  = sym(d_XG0);
    float* pSKIP = sym(d_SKIP);
    float* pKEYS = sym(d_KEYS);
    float* pHC   = sym(d_HC);
    float* pQ    = sym(d_Q);
    float* pXHE  = sym(d_XHE);
    float* pXH2  = sym(d_XH2);
    float* pCPR  = sym(d_CPR);
    float* pST0f = sym(d_ST0f);
    float* pST1f = sym(d_ST1f);
    float* pSKX0f= sym(d_SKX0f);
    float* pEX0f = sym(d_EX0f);
    float* pEX1f = sym(d_EX1f);
    __nv_bfloat16* pWSw = symb(d_WSw);
    float* pBST0 = sym(d_BST0);
    float* pBST1 = sym(d_BST1);
    float* pBSK0 = sym(d_BSK0);
    float* pBEX0 = sym(d_BEX0);
    float* pBEX1 = sym(d_BEX1);

    const int MB = BATCH*NSTMT;  // 640

    init_kernel<<<512, 256>>>();
    build_w<<<(512*H4 + 255)/256, 256>>>(st_Wx, sk_Wx, sk_Wh, ex_Wx, ex_Wh, ws);
    build_b<<<(H4 + 255)/256, 256>>>(st_b, sk_b, ex_b);

    // statement embedder: single LSTM step from zero state (h=0 => no Wh term)
    launch_gemm<1>(node_emb, pST0f, pBST0, nullptr, MB, HID, H4, pTMPH);
    launch_gemm<1>(pTMPH,    pST1f, pBST1, nullptr, MB, HID, H4, pSTMT);

    // xg0 = stmt @ skWx0 + skb0 (interleaved), shared by all 81 starts
    launch_gemm<0>(pSTMT, pSKX0f, pBSK0, pXG0, MB, HID, H4);

    // skip encoder: single persistent tensor-core kernel over all 80 steps
    skip_persist<<<NBP, 128>>>(ln_s, ln_b);

    // keys = skip @ ws + bs  (big parallel GEMM -> tensor cores)
    {
        int M = BATCH*NNODE*NNODE;
        dim3 g(HID/64, (M+63)/64);
        gemm_mma0<<<g, 128>>>(pSKIP, pWSw, bs, pKEYS, M, HID, HID);
    }

    // main interpreter loop
    for (int step = 0; step < NSTEP; step++) {
        launch_gemm<0>(pHC, wk, bk, pQ, CHAINS, H4, HID);
        attn_kernel<<<CHAINS, 256>>>(w1, b1, step);
        props_kernel<<<CHAINS, 256>>>();
        launch_gemm<4>(pXHE, pEX0f, pBEX0, nullptr, CHAINS, 512, H4,
                       pCPR, pHC, pXH2);
        launch_gemm<5>(pXH2, pEX1f, pBEX1, nullptr, CHAINS, 512, H4,
                       pCPR, pHC, nullptr);
    }

    out_kernel<<<(VOCAB + 255)/256, 256>>>(exit_idx, wo, bo, out);
}